// round 6
// baseline (speedup 1.0000x reference)
#include <cuda_runtime.h>
#include <cuda_bf16.h>
#include <cstdint>

#define BATCH 8
#define SEQ   2048
#define CH    512
#define ROWS  (BATCH * SEQ)          // 16384
#define SCALE 0.25f
#define RC    ((size_t)ROWS * CH)    // 8388608
#define SS    ((size_t)BATCH * SEQ * SEQ)

// ---------------- persistent scratch (module-static, allowed) ----------------
__device__ __nv_bfloat16 g_Ihi[3 * RC], g_Ilo[3 * RC];          // split inputs q,k,v
__device__ __nv_bfloat16 g_Whi[3 * CH * CH], g_Wlo[3 * CH * CH];// split weights
__device__ __nv_bfloat16 g_Qhi[RC], g_Qlo[RC];                  // proj outputs (Q pre-scaled)
__device__ __nv_bfloat16 g_Khi[RC], g_Klo[RC];
__device__ __nv_bfloat16 g_Vhi[RC], g_Vlo[RC];
__device__ float         g_S[SS];                               // raw scores
__device__ __nv_bfloat16 g_Shi[SS], g_Slo[SS];                  // split softmax probs

// ---------------- smem layout: 2 stages x (Ahi,Alo,Bhi,Blo) ----------------
#define LDA         40        // A smem pitch, elems (80 B rows)
#define LDBT        136       // trans-B smem pitch, elems (272 B rows)
#define MAT_BYTES   10240
#define OFF_AHI     0
#define OFF_ALO     10240
#define OFF_BHI     20480
#define OFF_BLO     30720
#define STAGE_BYTES 40960
#define SMEM_TOTAL  (2 * STAGE_BYTES)

extern __shared__ char dsmem[];

// ---------------- PTX helpers ----------------
__device__ __forceinline__ uint32_t smem_u32(const void* p) {
    uint32_t a;
    asm("{ .reg .u64 t; cvta.to.shared.u64 t, %1; cvt.u32.u64 %0, t; }"
        : "=r"(a) : "l"(p));
    return a;
}
__device__ __forceinline__ void cp16(uint32_t dst, const void* src) {
    asm volatile("cp.async.cg.shared.global [%0], [%1], 16;" :: "r"(dst), "l"(src));
}
#define CP_COMMIT() asm volatile("cp.async.commit_group;" ::: "memory")
#define CP_WAIT0()  asm volatile("cp.async.wait_group 0;" ::: "memory")
#define CP_WAIT1()  asm volatile("cp.async.wait_group 1;" ::: "memory")

#define LDMATRIX_X4(r0, r1, r2, r3, addr) \
    asm volatile("ldmatrix.sync.aligned.m8n8.x4.shared.b16 {%0,%1,%2,%3}, [%4];" \
                 : "=r"(r0), "=r"(r1), "=r"(r2), "=r"(r3) : "r"(addr))
#define LDMATRIX_X4_T(r0, r1, r2, r3, addr) \
    asm volatile("ldmatrix.sync.aligned.m8n8.x4.trans.shared.b16 {%0,%1,%2,%3}, [%4];" \
                 : "=r"(r0), "=r"(r1), "=r"(r2), "=r"(r3) : "r"(addr))

__device__ __forceinline__ void mma_bf16(float* c,
                                         uint32_t a0, uint32_t a1, uint32_t a2, uint32_t a3,
                                         uint32_t b0, uint32_t b1) {
    asm volatile(
        "mma.sync.aligned.m16n8k16.row.col.f32.bf16.bf16.f32 "
        "{%0,%1,%2,%3}, {%4,%5,%6,%7}, {%8,%9}, {%0,%1,%2,%3};"
        : "+f"(c[0]), "+f"(c[1]), "+f"(c[2]), "+f"(c[3])
        : "r"(a0), "r"(a1), "r"(a2), "r"(a3), "r"(b0), "r"(b1));
}

__device__ __forceinline__ void split2(float x, float y, uint32_t& hi, uint32_t& lo) {
    __nv_bfloat16 hx = __float2bfloat16(x);
    __nv_bfloat16 hy = __float2bfloat16(y);
    __nv_bfloat16 lx = __float2bfloat16(x - __bfloat162float(hx));
    __nv_bfloat16 ly = __float2bfloat16(y - __bfloat162float(hy));
    __nv_bfloat162 H = __halves2bfloat162(hx, hy);
    __nv_bfloat162 L = __halves2bfloat162(lx, ly);
    hi = *reinterpret_cast<uint32_t*>(&H);
    lo = *reinterpret_cast<uint32_t*>(&L);
}

// ---------------- tile loaders (cp.async) ----------------
__device__ __forceinline__ void ld_tileA(
    uint32_t sb, const __nv_bfloat16* Ahi, const __nv_bfloat16* Alo,
    int ldA, int rowBlock, int k0, int tid)
{
#pragma unroll
    for (int i = 0; i < 2; i++) {
        int c = i * 256 + tid;            // 512 chunks: 128 rows x 4
        int r = c >> 2, j = c & 3;
        size_t g = (size_t)(rowBlock + r) * ldA + k0 + j * 8;
        uint32_t d = r * 80 + j * 16;
        cp16(sb + OFF_AHI + d, Ahi + g);
        cp16(sb + OFF_ALO + d, Alo + g);
    }
}
// B K-major [n][k] source (non-trans ldmatrix)
__device__ __forceinline__ void ld_tileB_k(
    uint32_t sb, const __nv_bfloat16* Bhi, const __nv_bfloat16* Blo,
    int ldB, int colBlock, int k0, int tid)
{
#pragma unroll
    for (int i = 0; i < 2; i++) {
        int c = i * 256 + tid;
        int r = c >> 2, j = c & 3;
        size_t g = (size_t)(colBlock + r) * ldB + k0 + j * 8;
        uint32_t d = r * 80 + j * 16;
        cp16(sb + OFF_BHI + d, Bhi + g);
        cp16(sb + OFF_BLO + d, Blo + g);
    }
}
// B MN-major [k][n] source (trans ldmatrix): smem [32][136]
__device__ __forceinline__ void ld_tileB_t(
    uint32_t sb, const __nv_bfloat16* Bhi, const __nv_bfloat16* Blo,
    int ldB, int colBlock, int k0, int tid)
{
#pragma unroll
    for (int i = 0; i < 2; i++) {
        int c = i * 256 + tid;            // 512 chunks: 32 rows x 16
        int k = c >> 4, j = c & 15;
        size_t g = (size_t)(k0 + k) * ldB + colBlock + j * 8;
        uint32_t d = k * 272 + j * 16;
        cp16(sb + OFF_BHI + d, Bhi + g);
        cp16(sb + OFF_BLO + d, Blo + g);
    }
}

// ---------------- GEMM core: 128x128 tile, BK=32, 3-term split ----------------
// BT=false: B from [n][k]; BT=true: B from [k][n] via ldmatrix.trans.
// B fragments double-buffered across the np loop; MMA issue is TERM-MAJOR so
// consecutive HMMAs never share an accumulator (RAW chain distance = 4).
template<bool BT>
__device__ __forceinline__ void tc_core(
    const __nv_bfloat16* __restrict__ Ahi, const __nv_bfloat16* __restrict__ Alo,
    const __nv_bfloat16* __restrict__ Bhi, const __nv_bfloat16* __restrict__ Blo,
    int K_total, int ldB, int rowBlock, int colBlock,
    float acc[2][8][4])
{
    const int tid  = threadIdx.x;
    const int lane = tid & 31;
    const int wid  = tid >> 5;
    const int warpRow = wid & 3;
    const int warpCol = wid >> 2;

    const uint32_t sbase = smem_u32(dsmem);

#pragma unroll
    for (int mt = 0; mt < 2; mt++)
#pragma unroll
        for (int nt = 0; nt < 8; nt++)
#pragma unroll
            for (int e = 0; e < 4; e++) acc[mt][nt][e] = 0.f;

    // ldmatrix per-thread byte offsets
    const uint32_t aOff = ((warpRow * 32 + (lane & 15)) * LDA + ((lane >> 4) << 3)) * 2;
    const uint32_t bOffK = ((warpCol * 64 + ((lane >> 4) << 3) + (lane & 7)) * LDA
                           + (((lane >> 3) & 1) << 3)) * 2;
    const uint32_t bOffT = ((lane & 15) * LDBT + warpCol * 64 + ((lane >> 4) << 3)) * 2;

    const int ntiles = K_total >> 5;

    // prologue: stages 0,1
    ld_tileA(sbase, Ahi, Alo, K_total, rowBlock, 0, tid);
    if (BT) ld_tileB_t(sbase, Bhi, Blo, ldB, colBlock, 0, tid);
    else    ld_tileB_k(sbase, Bhi, Blo, ldB, colBlock, 0, tid);
    CP_COMMIT();
    ld_tileA(sbase + STAGE_BYTES, Ahi, Alo, K_total, rowBlock, 32, tid);
    if (BT) ld_tileB_t(sbase + STAGE_BYTES, Bhi, Blo, ldB, colBlock, 32, tid);
    else    ld_tileB_k(sbase + STAGE_BYTES, Bhi, Blo, ldB, colBlock, 32, tid);
    CP_COMMIT();

    for (int kt = 0; kt < ntiles; kt++) {
        if (kt + 1 < ntiles) { CP_WAIT1(); } else { CP_WAIT0(); }
        __syncthreads();

        const uint32_t sb = sbase + (kt & 1) * STAGE_BYTES;
#pragma unroll
        for (int ks = 0; ks < 2; ks++) {
            const int kb = ks * 16;
            uint32_t ah[2][4], al[2][4];
            uint32_t bh[2][4], bl[2][4];   // double-buffered B fragments

            // Issue A hi/lo and B(np=0) loads back-to-back.
#pragma unroll
            for (int mt = 0; mt < 2; mt++) {
                uint32_t ad = sb + aOff + (mt * 16 * LDA + kb) * 2;
                LDMATRIX_X4(ah[mt][0], ah[mt][1], ah[mt][2], ah[mt][3], ad + OFF_AHI);
                LDMATRIX_X4(al[mt][0], al[mt][1], al[mt][2], al[mt][3], ad + OFF_ALO);
            }
            if (BT) {
                uint32_t bd = sb + bOffT + (kb * LDBT) * 2;
                LDMATRIX_X4_T(bh[0][0], bh[0][1], bh[0][2], bh[0][3], bd + OFF_BHI);
                LDMATRIX_X4_T(bl[0][0], bl[0][1], bl[0][2], bl[0][3], bd + OFF_BLO);
            } else {
                uint32_t bd = sb + bOffK + (kb) * 2;
                LDMATRIX_X4(bh[0][0], bh[0][1], bh[0][2], bh[0][3], bd + OFF_BHI);
                LDMATRIX_X4(bl[0][0], bl[0][1], bl[0][2], bl[0][3], bd + OFF_BLO);
            }

#pragma unroll
            for (int np = 0; np < 4; np++) {
                const int cur = np & 1;
                const int nxt = cur ^ 1;
                // Prefetch B(np+1) while MMAs consume B(np).
                if (np < 3) {
                    if (BT) {
                        uint32_t bd = sb + bOffT + (kb * LDBT + (np + 1) * 16) * 2;
                        LDMATRIX_X4_T(bh[nxt][0], bh[nxt][1], bh[nxt][2], bh[nxt][3], bd + OFF_BHI);
                        LDMATRIX_X4_T(bl[nxt][0], bl[nxt][1], bl[nxt][2], bl[nxt][3], bd + OFF_BLO);
                    } else {
                        uint32_t bd = sb + bOffK + ((np + 1) * 16 * LDA + kb) * 2;
                        LDMATRIX_X4(bh[nxt][0], bh[nxt][1], bh[nxt][2], bh[nxt][3], bd + OFF_BHI);
                        LDMATRIX_X4(bl[nxt][0], bl[nxt][1], bl[nxt][2], bl[nxt][3], bd + OFF_BLO);
                    }
                }
                // TERM-MAJOR: 4 independent accumulators between revisits.
                // term 0: hi*hi, term 1: lo*hi, term 2: hi*lo.
#pragma unroll
                for (int term = 0; term < 3; term++) {
#pragma unroll
                    for (int half = 0; half < 2; half++) {
                        const int nt = np * 2 + half;
                        uint32_t b0 = (term == 2) ? bl[cur][half * 2]     : bh[cur][half * 2];
                        uint32_t b1 = (term == 2) ? bl[cur][half * 2 + 1] : bh[cur][half * 2 + 1];
#pragma unroll
                        for (int mt = 0; mt < 2; mt++) {
                            if (term == 1)
                                mma_bf16(acc[mt][nt], al[mt][0], al[mt][1], al[mt][2], al[mt][3], b0, b1);
                            else
                                mma_bf16(acc[mt][nt], ah[mt][0], ah[mt][1], ah[mt][2], ah[mt][3], b0, b1);
                        }
                    }
                }
            }
        }
        __syncthreads();

        if (kt + 2 < ntiles) {
            const uint32_t sb2 = sbase + (kt & 1) * STAGE_BYTES;
            const int k0 = (kt + 2) * 32;
            ld_tileA(sb2, Ahi, Alo, K_total, rowBlock, k0, tid);
            if (BT) ld_tileB_t(sb2, Bhi, Blo, ldB, colBlock, k0, tid);
            else    ld_tileB_k(sb2, Bhi, Blo, ldB, colBlock, k0, tid);
            CP_COMMIT();
        }
    }
}

// ---------------- Stage 0: split inputs + weights to bf16 hi/lo ----------------
__global__ __launch_bounds__(256) void pre_kernel(
    const float* __restrict__ q, const float* __restrict__ k, const float* __restrict__ v,
    const float* __restrict__ Wq, const float* __restrict__ Wk, const float* __restrict__ Wv)
{
    const int z = blockIdx.z;
    const float* src;
    __nv_bfloat16 *hi, *lo;
    size_t n4;
    if (z < 3) {
        src = (z == 0) ? q : (z == 1) ? k : v;
        hi = g_Ihi + (size_t)z * RC; lo = g_Ilo + (size_t)z * RC;
        n4 = RC / 4;
    } else {
        int w = z - 3;
        src = (w == 0) ? Wq : (w == 1) ? Wk : Wv;
        hi = g_Whi + (size_t)w * CH * CH; lo = g_Wlo + (size_t)w * CH * CH;
        n4 = (size_t)CH * CH / 4;
    }
    size_t i4 = (size_t)blockIdx.x * 256 + threadIdx.x;
    if (i4 >= n4) return;
    float4 val = ((const float4*)src)[i4];
    uint32_t h01, l01, h23, l23;
    split2(val.x, val.y, h01, l01);
    split2(val.z, val.w, h23, l23);
    *(uint2*)(hi + i4 * 4) = make_uint2(h01, h23);
    *(uint2*)(lo + i4 * 4) = make_uint2(l01, l23);
}

// ---------------- Stage 1: projections (output split bf16; Q pre-scaled) -------
__global__ __launch_bounds__(256, 2) void proj_kernel(
    const float* __restrict__ bq, const float* __restrict__ bk, const float* __restrict__ bv)
{
    const int z = blockIdx.z;
    const __nv_bfloat16* Ahi = g_Ihi + (size_t)z * RC;
    const __nv_bfloat16* Alo = g_Ilo + (size_t)z * RC;
    const __nv_bfloat16* Bhi = g_Whi + (size_t)z * CH * CH;
    const __nv_bfloat16* Blo = g_Wlo + (size_t)z * CH * CH;
    const float* bias = (z == 0) ? bq : (z == 1) ? bk : bv;
    __nv_bfloat16* Chi = (z == 0) ? g_Qhi : (z == 1) ? g_Khi : g_Vhi;
    __nv_bfloat16* Clo = (z == 0) ? g_Qlo : (z == 1) ? g_Klo : g_Vlo;
    const float alpha = (z == 0) ? SCALE : 1.0f;

    const int rowBlock = blockIdx.y * 128;
    const int colBlock = blockIdx.x * 128;

    float acc[2][8][4];
    tc_core<true>(Ahi, Alo, Bhi, Blo, CH, CH, rowBlock, colBlock, acc);

    const int lane = threadIdx.x & 31;
    const int wid  = threadIdx.x >> 5;
    const int warpRow = wid & 3, warpCol = wid >> 2;
#pragma unroll
    for (int mt = 0; mt < 2; mt++) {
#pragma unroll
        for (int nt = 0; nt < 8; nt++) {
            int row = rowBlock + warpRow * 32 + mt * 16 + (lane >> 2);
            int col = colBlock + warpCol * 64 + nt * 8 + (lane & 3) * 2;
            float2 b = *(const float2*)(bias + col);
            float x0 = (acc[mt][nt][0] + b.x) * alpha;
            float y0 = (acc[mt][nt][1] + b.y) * alpha;
            float x1 = (acc[mt][nt][2] + b.x) * alpha;
            float y1 = (acc[mt][nt][3] + b.y) * alpha;
            uint32_t h, l;
            split2(x0, y0, h, l);
            *(uint32_t*)(Chi + (size_t)row * CH + col) = h;
            *(uint32_t*)(Clo + (size_t)row * CH + col) = l;
            split2(x1, y1, h, l);
            *(uint32_t*)(Chi + (size_t)(row + 8) * CH + col) = h;
            *(uint32_t*)(Clo + (size_t)(row + 8) * CH + col) = l;
        }
    }
}

// ---------------- Stage 2: S = Q * K^T (scale already folded into Q) ----------
__global__ __launch_bounds__(256, 2) void qk_kernel()
{
    const int z = blockIdx.z;
    const size_t po = (size_t)z * SEQ * CH;
    float* S = g_S + (size_t)z * SEQ * SEQ;
    const int rowBlock = blockIdx.y * 128;
    const int colBlock = blockIdx.x * 128;

    float acc[2][8][4];
    tc_core<false>(g_Qhi + po, g_Qlo + po, g_Khi + po, g_Klo + po,
                   CH, CH, rowBlock, colBlock, acc);

    const int lane = threadIdx.x & 31;
    const int wid  = threadIdx.x >> 5;
    const int warpRow = wid & 3, warpCol = wid >> 2;
#pragma unroll
    for (int mt = 0; mt < 2; mt++) {
#pragma unroll
        for (int nt = 0; nt < 8; nt++) {
            int row = rowBlock + warpRow * 32 + mt * 16 + (lane >> 2);
            int col = colBlock + warpCol * 64 + nt * 8 + (lane & 3) * 2;
            *(float2*)(S + (size_t)row * SEQ + col) =
                make_float2(acc[mt][nt][0], acc[mt][nt][1]);
            *(float2*)(S + (size_t)(row + 8) * SEQ + col) =
                make_float2(acc[mt][nt][2], acc[mt][nt][3]);
        }
    }
}

// ---------------- Stage 3: softmax -> split bf16 probs ----------------
__global__ __launch_bounds__(256) void softmax_kernel()
{
    __shared__ float red[8];
    const size_t ro = (size_t)blockIdx.x * SEQ;
    const float* row = g_S + ro;
    const int tid = threadIdx.x;

    float vals[8];
    float m = -3.0e38f;
#pragma unroll
    for (int i = 0; i < 8; i++) {
        vals[i] = row[tid + i * 256];
        m = fmaxf(m, vals[i]);
    }
#pragma unroll
    for (int o = 16; o; o >>= 1) m = fmaxf(m, __shfl_xor_sync(0xffffffffu, m, o));
    if ((tid & 31) == 0) red[tid >> 5] = m;
    __syncthreads();
    float bm = red[0];
#pragma unroll
    for (int i = 1; i < 8; i++) bm = fmaxf(bm, red[i]);
    __syncthreads();

    float s = 0.f;
#pragma unroll
    for (int i = 0; i < 8; i++) {
        vals[i] = __expf(vals[i] - bm);
        s += vals[i];
    }
#pragma unroll
    for (int o = 16; o; o >>= 1) s += __shfl_xor_sync(0xffffffffu, s, o);
    if ((tid & 31) == 0) red[tid >> 5] = s;
    __syncthreads();
    float tot = 0.f;
#pragma unroll
    for (int i = 0; i < 8; i++) tot += red[i];
    float inv = 1.0f / tot;
#pragma unroll
    for (int i = 0; i < 8; i++) {
        float p = vals[i] * inv;
        __nv_bfloat16 h = __float2bfloat16(p);
        __nv_bfloat16 l = __float2bfloat16(p - __bfloat162float(h));
        g_Shi[ro + tid + i * 256] = h;
        g_Slo[ro + tid + i * 256] = l;
    }
}

// ---------------- Stage 4: O = P * V ----------------
__global__ __launch_bounds__(256, 2) void pv_kernel(float* __restrict__ out)
{
    const int z = blockIdx.z;
    const size_t so = (size_t)z * SEQ * SEQ;
    const size_t vo = (size_t)z * SEQ * CH;
    const int rowBlock = blockIdx.y * 128;
    const int colBlock = blockIdx.x * 128;

    float acc[2][8][4];
    tc_core<true>(g_Shi + so, g_Slo + so, g_Vhi + vo, g_Vlo + vo,
                  SEQ, CH, rowBlock, colBlock, acc);

    float* O = out + vo;
    const int lane = threadIdx.x & 31;
    const int wid  = threadIdx.x >> 5;
    const int warpRow = wid & 3, warpCol = wid >> 2;
#pragma unroll
    for (int mt = 0; mt < 2; mt++) {
#pragma unroll
        for (int nt = 0; nt < 8; nt++) {
            int row = rowBlock + warpRow * 32 + mt * 16 + (lane >> 2);
            int col = colBlock + warpCol * 64 + nt * 8 + (lane & 3) * 2;
            *(float2*)(O + (size_t)row * CH + col) =
                make_float2(acc[mt][nt][0], acc[mt][nt][1]);
            *(float2*)(O + (size_t)(row + 8) * CH + col) =
                make_float2(acc[mt][nt][2], acc[mt][nt][3]);
        }
    }
}

// ---------------------------------------------------------------------------
extern "C" void kernel_launch(void* const* d_in, const int* in_sizes, int n_in,
                              void* d_out, int out_size)
{
    const float* q  = (const float*)d_in[0];
    const float* k  = (const float*)d_in[1];
    const float* v  = (const float*)d_in[2];
    const float* Wq = (const float*)d_in[3];
    const float* bq = (const float*)d_in[4];
    const float* Wk = (const float*)d_in[5];
    const float* bk = (const float*)d_in[6];
    const float* Wv = (const float*)d_in[7];
    const float* bv = (const float*)d_in[8];
    float* out = (float*)d_out;

    static int configured = 0;
    if (!configured) {
        cudaFuncSetAttribute(proj_kernel, cudaFuncAttributeMaxDynamicSharedMemorySize, SMEM_TOTAL);
        cudaFuncSetAttribute(qk_kernel,   cudaFuncAttributeMaxDynamicSharedMemorySize, SMEM_TOTAL);
        cudaFuncSetAttribute(pv_kernel,   cudaFuncAttributeMaxDynamicSharedMemorySize, SMEM_TOTAL);
        configured = 1;
    }

    dim3 gPre(8192, 1, 6);
    pre_kernel<<<gPre, 256>>>(q, k, v, Wq, Wk, Wv);

    dim3 gProj(CH / 128, ROWS / 128, 3);      // (4, 128, 3)
    proj_kernel<<<gProj, 256, SMEM_TOTAL>>>(bq, bk, bv);

    dim3 gQK(SEQ / 128, SEQ / 128, BATCH);    // (16, 16, 8)
    qk_kernel<<<gQK, 256, SMEM_TOTAL>>>();

    softmax_kernel<<<ROWS, 256>>>();          // 16384 rows

    dim3 gPV(CH / 128, SEQ / 128, BATCH);     // (4, 16, 8)
    pv_kernel<<<gPV, 256, SMEM_TOTAL>>>(out);
}

// round 7
// speedup vs baseline: 1.4638x; 1.4638x over previous
#include <cuda_runtime.h>
#include <cuda_bf16.h>
#include <cuda_fp16.h>
#include <cstdint>

#define BATCH 8
#define SEQ   2048
#define CH    512
#define ROWS  (BATCH * SEQ)          // 16384
#define SCALE 0.25f
#define RC    ((size_t)ROWS * CH)    // 8388608
#define SS    ((size_t)BATCH * SEQ * SEQ)

// ---------------- persistent scratch ----------------
__device__ __nv_bfloat16 g_Ihi[3 * RC], g_Ilo[3 * RC];          // split inputs q,k,v (bf16)
__device__ __nv_bfloat16 g_Whi[3 * CH * CH], g_Wlo[3 * CH * CH];// split weights (bf16)
__device__ __half g_Qh[RC], g_Ql[RC];   // Q projected, pre-scaled, fp16 hi/lo
__device__ __half g_Kh[RC];             // K projected, single fp16
__device__ __half g_Vh[RC];             // V projected, single fp16
__device__ float  g_S[SS];              // raw scores fp32
__device__ __half g_P[SS];              // softmax probs, single fp16

// ---------------- smem pitches ----------------
#define LDA   40        // K-major pitch, elems (80 B rows)
#define LDBT  136       // trans-B pitch, elems (272 B rows)

extern __shared__ char dsmem[];

// ---------------- PTX helpers ----------------
__device__ __forceinline__ uint32_t smem_u32(const void* p) {
    uint32_t a;
    asm("{ .reg .u64 t; cvta.to.shared.u64 t, %1; cvt.u32.u64 %0, t; }"
        : "=r"(a) : "l"(p));
    return a;
}
__device__ __forceinline__ void cp16(uint32_t dst, const void* src) {
    asm volatile("cp.async.cg.shared.global [%0], [%1], 16;" :: "r"(dst), "l"(src));
}
#define CP_COMMIT() asm volatile("cp.async.commit_group;" ::: "memory")
#define CP_WAIT0()  asm volatile("cp.async.wait_group 0;" ::: "memory")
#define CP_WAIT1()  asm volatile("cp.async.wait_group 1;" ::: "memory")

#define LDMATRIX_X4(r0, r1, r2, r3, addr) \
    asm volatile("ldmatrix.sync.aligned.m8n8.x4.shared.b16 {%0,%1,%2,%3}, [%4];" \
                 : "=r"(r0), "=r"(r1), "=r"(r2), "=r"(r3) : "r"(addr))
#define LDMATRIX_X4_T(r0, r1, r2, r3, addr) \
    asm volatile("ldmatrix.sync.aligned.m8n8.x4.trans.shared.b16 {%0,%1,%2,%3}, [%4];" \
                 : "=r"(r0), "=r"(r1), "=r"(r2), "=r"(r3) : "r"(addr))

__device__ __forceinline__ void mma_bf16(float* c,
                                         uint32_t a0, uint32_t a1, uint32_t a2, uint32_t a3,
                                         uint32_t b0, uint32_t b1) {
    asm volatile(
        "mma.sync.aligned.m16n8k16.row.col.f32.bf16.bf16.f32 "
        "{%0,%1,%2,%3}, {%4,%5,%6,%7}, {%8,%9}, {%0,%1,%2,%3};"
        : "+f"(c[0]), "+f"(c[1]), "+f"(c[2]), "+f"(c[3])
        : "r"(a0), "r"(a1), "r"(a2), "r"(a3), "r"(b0), "r"(b1));
}
__device__ __forceinline__ void mma_fp16(float* c,
                                         uint32_t a0, uint32_t a1, uint32_t a2, uint32_t a3,
                                         uint32_t b0, uint32_t b1) {
    asm volatile(
        "mma.sync.aligned.m16n8k16.row.col.f32.f16.f16.f32 "
        "{%0,%1,%2,%3}, {%4,%5,%6,%7}, {%8,%9}, {%0,%1,%2,%3};"
        : "+f"(c[0]), "+f"(c[1]), "+f"(c[2]), "+f"(c[3])
        : "r"(a0), "r"(a1), "r"(a2), "r"(a3), "r"(b0), "r"(b1));
}

__device__ __forceinline__ void split2(float x, float y, uint32_t& hi, uint32_t& lo) {
    __nv_bfloat16 hx = __float2bfloat16(x);
    __nv_bfloat16 hy = __float2bfloat16(y);
    __nv_bfloat16 lx = __float2bfloat16(x - __bfloat162float(hx));
    __nv_bfloat16 ly = __float2bfloat16(y - __bfloat162float(hy));
    __nv_bfloat162 H = __halves2bfloat162(hx, hy);
    __nv_bfloat162 L = __halves2bfloat162(lx, ly);
    hi = *reinterpret_cast<uint32_t*>(&H);
    lo = *reinterpret_cast<uint32_t*>(&L);
}
__device__ __forceinline__ void split2h(float x, float y, uint32_t& hi, uint32_t& lo) {
    __half hx = __float2half(x);
    __half hy = __float2half(y);
    __half lx = __float2half(x - __half2float(hx));
    __half ly = __float2half(y - __half2float(hy));
    __half2 H = __halves2half2(hx, hy);
    __half2 L = __halves2half2(lx, ly);
    hi = *reinterpret_cast<uint32_t*>(&H);
    lo = *reinterpret_cast<uint32_t*>(&L);
}

// ---------------- tile loaders (cp.async, 16-bit element arrays) ----------------
// K-major [row][k] tile: 128 rows x 32 k, dst pitch 80B.
__device__ __forceinline__ void ld_km(uint32_t dst, const __nv_bfloat16* src,
                                      int ld, int rowBlock, int k0, int tid)
{
#pragma unroll
    for (int i = 0; i < 2; i++) {
        int c = i * 256 + tid;            // 512 chunks: 128 rows x 4
        int r = c >> 2, j = c & 3;
        cp16(dst + r * 80 + j * 16, src + (size_t)(rowBlock + r) * ld + k0 + j * 8);
    }
}
// MN-major [k][n] tile: 32 k-rows x 128 n, dst pitch 272B.
__device__ __forceinline__ void ld_mn(uint32_t dst, const __nv_bfloat16* src,
                                      int ld, int colBlock, int k0, int tid)
{
#pragma unroll
    for (int i = 0; i < 2; i++) {
        int c = i * 256 + tid;            // 512 chunks: 32 rows x 16
        int k = c >> 4, j = c & 15;
        cp16(dst + k * 272 + j * 16, src + (size_t)(k0 + k) * ld + colBlock + j * 8);
    }
}

// ================= proj core: bf16 3-term split (R5-proven, unchanged) =========
#define P_OFF_AHI   0
#define P_OFF_ALO   10240
#define P_OFF_BHI   20480
#define P_OFF_BLO   30720
#define P_STAGE     40960

__device__ __forceinline__ void tc_core3(
    const __nv_bfloat16* __restrict__ Ahi, const __nv_bfloat16* __restrict__ Alo,
    const __nv_bfloat16* __restrict__ Bhi, const __nv_bfloat16* __restrict__ Blo,
    int K_total, int ldB, int rowBlock, int colBlock,
    float acc[2][8][4])
{
    const int tid  = threadIdx.x;
    const int lane = tid & 31;
    const int wid  = tid >> 5;
    const int warpRow = wid & 3;
    const int warpCol = wid >> 2;
    const uint32_t sbase = smem_u32(dsmem);

#pragma unroll
    for (int mt = 0; mt < 2; mt++)
#pragma unroll
        for (int nt = 0; nt < 8; nt++)
#pragma unroll
            for (int e = 0; e < 4; e++) acc[mt][nt][e] = 0.f;

    const uint32_t aOff = ((warpRow * 32 + (lane & 15)) * LDA + ((lane >> 4) << 3)) * 2;
    const uint32_t bOffT = ((lane & 15) * LDBT + warpCol * 64 + ((lane >> 4) << 3)) * 2;

    const int ntiles = K_total >> 5;

    ld_km(sbase + P_OFF_AHI, Ahi, K_total, rowBlock, 0, tid);
    ld_km(sbase + P_OFF_ALO, Alo, K_total, rowBlock, 0, tid);
    ld_mn(sbase + P_OFF_BHI, Bhi, ldB, colBlock, 0, tid);
    ld_mn(sbase + P_OFF_BLO, Blo, ldB, colBlock, 0, tid);
    CP_COMMIT();
    ld_km(sbase + P_STAGE + P_OFF_AHI, Ahi, K_total, rowBlock, 32, tid);
    ld_km(sbase + P_STAGE + P_OFF_ALO, Alo, K_total, rowBlock, 32, tid);
    ld_mn(sbase + P_STAGE + P_OFF_BHI, Bhi, ldB, colBlock, 32, tid);
    ld_mn(sbase + P_STAGE + P_OFF_BLO, Blo, ldB, colBlock, 32, tid);
    CP_COMMIT();

    for (int kt = 0; kt < ntiles; kt++) {
        if (kt + 1 < ntiles) { CP_WAIT1(); } else { CP_WAIT0(); }
        __syncthreads();

        const uint32_t sb = sbase + (kt & 1) * P_STAGE;
#pragma unroll
        for (int ks = 0; ks < 2; ks++) {
            const int kb = ks * 16;
            uint32_t ah[2][4], al[2][4];
            uint32_t bh[2][4], bl[2][4];
#pragma unroll
            for (int mt = 0; mt < 2; mt++) {
                uint32_t ad = sb + aOff + (mt * 16 * LDA + kb) * 2;
                LDMATRIX_X4(ah[mt][0], ah[mt][1], ah[mt][2], ah[mt][3], ad + P_OFF_AHI);
                LDMATRIX_X4(al[mt][0], al[mt][1], al[mt][2], al[mt][3], ad + P_OFF_ALO);
            }
            {
                uint32_t bd = sb + bOffT + (kb * LDBT) * 2;
                LDMATRIX_X4_T(bh[0][0], bh[0][1], bh[0][2], bh[0][3], bd + P_OFF_BHI);
                LDMATRIX_X4_T(bl[0][0], bl[0][1], bl[0][2], bl[0][3], bd + P_OFF_BLO);
            }
#pragma unroll
            for (int np = 0; np < 4; np++) {
                const int cur = np & 1;
                const int nxt = cur ^ 1;
                if (np < 3) {
                    uint32_t bd = sb + bOffT + (kb * LDBT + (np + 1) * 16) * 2;
                    LDMATRIX_X4_T(bh[nxt][0], bh[nxt][1], bh[nxt][2], bh[nxt][3], bd + P_OFF_BHI);
                    LDMATRIX_X4_T(bl[nxt][0], bl[nxt][1], bl[nxt][2], bl[nxt][3], bd + P_OFF_BLO);
                }
#pragma unroll
                for (int half = 0; half < 2; half++) {
                    uint32_t bh0 = bh[cur][half * 2], bh1 = bh[cur][half * 2 + 1];
                    uint32_t bl0 = bl[cur][half * 2], bl1 = bl[cur][half * 2 + 1];
#pragma unroll
                    for (int mt = 0; mt < 2; mt++) {
                        int nt = np * 2 + half;
                        mma_bf16(acc[mt][nt], ah[mt][0], ah[mt][1], ah[mt][2], ah[mt][3], bh0, bh1);
                        mma_bf16(acc[mt][nt], ah[mt][0], ah[mt][1], ah[mt][2], ah[mt][3], bl0, bl1);
                        mma_bf16(acc[mt][nt], al[mt][0], al[mt][1], al[mt][2], al[mt][3], bh0, bh1);
                    }
                }
            }
        }
        __syncthreads();

        if (kt + 2 < ntiles) {
            const uint32_t sb2 = sbase + (kt & 1) * P_STAGE;
            const int k0 = (kt + 2) * 32;
            ld_km(sb2 + P_OFF_AHI, Ahi, K_total, rowBlock, k0, tid);
            ld_km(sb2 + P_OFF_ALO, Alo, K_total, rowBlock, k0, tid);
            ld_mn(sb2 + P_OFF_BHI, Bhi, ldB, colBlock, k0, tid);
            ld_mn(sb2 + P_OFF_BLO, Blo, ldB, colBlock, k0, tid);
            CP_COMMIT();
        }
    }
}

// ================= Stage 0: split inputs + weights to bf16 hi/lo ===============
__global__ __launch_bounds__(256) void pre_kernel(
    const float* __restrict__ q, const float* __restrict__ k, const float* __restrict__ v,
    const float* __restrict__ Wq, const float* __restrict__ Wk, const float* __restrict__ Wv)
{
    const int z = blockIdx.z;
    const float* src;
    __nv_bfloat16 *hi, *lo;
    size_t n4;
    if (z < 3) {
        src = (z == 0) ? q : (z == 1) ? k : v;
        hi = g_Ihi + (size_t)z * RC; lo = g_Ilo + (size_t)z * RC;
        n4 = RC / 4;
    } else {
        int w = z - 3;
        src = (w == 0) ? Wq : (w == 1) ? Wk : Wv;
        hi = g_Whi + (size_t)w * CH * CH; lo = g_Wlo + (size_t)w * CH * CH;
        n4 = (size_t)CH * CH / 4;
    }
    size_t i4 = (size_t)blockIdx.x * 256 + threadIdx.x;
    if (i4 >= n4) return;
    float4 val = ((const float4*)src)[i4];
    uint32_t h01, l01, h23, l23;
    split2(val.x, val.y, h01, l01);
    split2(val.z, val.w, h23, l23);
    *(uint2*)(hi + i4 * 4) = make_uint2(h01, h23);
    *(uint2*)(lo + i4 * 4) = make_uint2(l01, l23);
}

// ================= Stage 1: projections ========================================
// z=0: Q -> fp16 hi/lo, pre-scaled by 0.25. z=1: K -> fp16. z=2: V -> fp16.
__global__ __launch_bounds__(256, 2) void proj_kernel(
    const float* __restrict__ bq, const float* __restrict__ bk, const float* __restrict__ bv)
{
    const int z = blockIdx.z;
    const __nv_bfloat16* Ahi = g_Ihi + (size_t)z * RC;
    const __nv_bfloat16* Alo = g_Ilo + (size_t)z * RC;
    const __nv_bfloat16* Bhi = g_Whi + (size_t)z * CH * CH;
    const __nv_bfloat16* Blo = g_Wlo + (size_t)z * CH * CH;
    const float* bias = (z == 0) ? bq : (z == 1) ? bk : bv;

    const int rowBlock = blockIdx.y * 128;
    const int colBlock = blockIdx.x * 128;

    float acc[2][8][4];
    tc_core3(Ahi, Alo, Bhi, Blo, CH, CH, rowBlock, colBlock, acc);

    const int lane = threadIdx.x & 31;
    const int wid  = threadIdx.x >> 5;
    const int warpRow = wid & 3, warpCol = wid >> 2;
#pragma unroll
    for (int mt = 0; mt < 2; mt++) {
#pragma unroll
        for (int nt = 0; nt < 8; nt++) {
            int row = rowBlock + warpRow * 32 + mt * 16 + (lane >> 2);
            int col = colBlock + warpCol * 64 + nt * 8 + (lane & 3) * 2;
            float2 b = *(const float2*)(bias + col);
            float x0 = acc[mt][nt][0] + b.x;
            float y0 = acc[mt][nt][1] + b.y;
            float x1 = acc[mt][nt][2] + b.x;
            float y1 = acc[mt][nt][3] + b.y;
            size_t o0 = (size_t)row * CH + col;
            size_t o1 = (size_t)(row + 8) * CH + col;
            if (z == 0) {
                uint32_t h, l;
                split2h(x0 * SCALE, y0 * SCALE, h, l);
                *(uint32_t*)(g_Qh + o0) = h;
                *(uint32_t*)(g_Ql + o0) = l;
                split2h(x1 * SCALE, y1 * SCALE, h, l);
                *(uint32_t*)(g_Qh + o1) = h;
                *(uint32_t*)(g_Ql + o1) = l;
            } else {
                __half* dst = (z == 1) ? g_Kh : g_Vh;
                __half2 p0 = __halves2half2(__float2half(x0), __float2half(y0));
                __half2 p1 = __halves2half2(__float2half(x1), __float2half(y1));
                *(__half2*)(dst + o0) = p0;
                *(__half2*)(dst + o1) = p1;
            }
        }
    }
}

// ================= Stage 2: S = Q*K^T (fp16 2-term: Qh,Ql x Kh) ================
#define Q_OFF_AH 0
#define Q_OFF_AL 10240
#define Q_OFF_B  20480
#define Q_STAGE  30720

__global__ __launch_bounds__(256, 2) void qk_kernel()
{
    const int z = blockIdx.z;
    const size_t po = (size_t)z * SEQ * CH;
    float* S = g_S + (size_t)z * SEQ * SEQ;
    const int rowBlock = blockIdx.y * 128;
    const int colBlock = blockIdx.x * 128;

    const __nv_bfloat16* Ah = (const __nv_bfloat16*)(g_Qh + po);
    const __nv_bfloat16* Al = (const __nv_bfloat16*)(g_Ql + po);
    const __nv_bfloat16* Bh = (const __nv_bfloat16*)(g_Kh + po);

    const int tid  = threadIdx.x;
    const int lane = tid & 31;
    const int wid  = tid >> 5;
    const int warpRow = wid & 3;
    const int warpCol = wid >> 2;
    const uint32_t sbase = smem_u32(dsmem);

    float acc[2][8][4];
#pragma unroll
    for (int mt = 0; mt < 2; mt++)
#pragma unroll
        for (int nt = 0; nt < 8; nt++)
#pragma unroll
            for (int e = 0; e < 4; e++) acc[mt][nt][e] = 0.f;

    const uint32_t aOff = ((warpRow * 32 + (lane & 15)) * LDA + ((lane >> 4) << 3)) * 2;
    const uint32_t bOff = ((warpCol * 64 + ((lane >> 4) << 3) + (lane & 7)) * LDA
                          + (((lane >> 3) & 1) << 3)) * 2;

    const int ntiles = CH >> 5;    // 16

    ld_km(sbase + Q_OFF_AH, Ah, CH, rowBlock, 0, tid);
    ld_km(sbase + Q_OFF_AL, Al, CH, rowBlock, 0, tid);
    ld_km(sbase + Q_OFF_B,  Bh, CH, colBlock, 0, tid);
    CP_COMMIT();
    ld_km(sbase + Q_STAGE + Q_OFF_AH, Ah, CH, rowBlock, 32, tid);
    ld_km(sbase + Q_STAGE + Q_OFF_AL, Al, CH, rowBlock, 32, tid);
    ld_km(sbase + Q_STAGE + Q_OFF_B,  Bh, CH, colBlock, 32, tid);
    CP_COMMIT();

    for (int kt = 0; kt < ntiles; kt++) {
        if (kt + 1 < ntiles) { CP_WAIT1(); } else { CP_WAIT0(); }
        __syncthreads();

        const uint32_t sb = sbase + (kt & 1) * Q_STAGE;
#pragma unroll
        for (int ks = 0; ks < 2; ks++) {
            const int kb = ks * 16;
            uint32_t ah[2][4], al[2][4];
#pragma unroll
            for (int mt = 0; mt < 2; mt++) {
                uint32_t ad = sb + aOff + (mt * 16 * LDA + kb) * 2;
                LDMATRIX_X4(ah[mt][0], ah[mt][1], ah[mt][2], ah[mt][3], ad + Q_OFF_AH);
                LDMATRIX_X4(al[mt][0], al[mt][1], al[mt][2], al[mt][3], ad + Q_OFF_AL);
            }
#pragma unroll
            for (int np = 0; np < 4; np++) {
                uint32_t bh[4];
                uint32_t bd = sb + Q_OFF_B + bOff + (np * 16 * LDA + kb) * 2;
                LDMATRIX_X4(bh[0], bh[1], bh[2], bh[3], bd);
#pragma unroll
                for (int half = 0; half < 2; half++) {
                    uint32_t b0 = bh[half * 2], b1 = bh[half * 2 + 1];
#pragma unroll
                    for (int mt = 0; mt < 2; mt++) {
                        int nt = np * 2 + half;
                        mma_fp16(acc[mt][nt], ah[mt][0], ah[mt][1], ah[mt][2], ah[mt][3], b0, b1);
                        mma_fp16(acc[mt][nt], al[mt][0], al[mt][1], al[mt][2], al[mt][3], b0, b1);
                    }
                }
            }
        }
        __syncthreads();

        if (kt + 2 < ntiles) {
            const uint32_t sb2 = sbase + (kt & 1) * Q_STAGE;
            const int k0 = (kt + 2) * 32;
            ld_km(sb2 + Q_OFF_AH, Ah, CH, rowBlock, k0, tid);
            ld_km(sb2 + Q_OFF_AL, Al, CH, rowBlock, k0, tid);
            ld_km(sb2 + Q_OFF_B,  Bh, CH, colBlock, k0, tid);
            CP_COMMIT();
        }
    }

#pragma unroll
    for (int mt = 0; mt < 2; mt++) {
#pragma unroll
        for (int nt = 0; nt < 8; nt++) {
            int row = rowBlock + warpRow * 32 + mt * 16 + (lane >> 2);
            int col = colBlock + warpCol * 64 + nt * 8 + (lane & 3) * 2;
            *(float2*)(S + (size_t)row * SEQ + col) =
                make_float2(acc[mt][nt][0], acc[mt][nt][1]);
            *(float2*)(S + (size_t)(row + 8) * SEQ + col) =
                make_float2(acc[mt][nt][2], acc[mt][nt][3]);
        }
    }
}

// ================= Stage 3: softmax -> single fp16 probs =======================
__global__ __launch_bounds__(256) void softmax_kernel()
{
    __shared__ float red[8];
    const size_t ro = (size_t)blockIdx.x * SEQ;
    const float* row = g_S + ro;
    const int tid = threadIdx.x;

    float vals[8];
    float m = -3.0e38f;
#pragma unroll
    for (int i = 0; i < 8; i++) {
        vals[i] = row[tid + i * 256];
        m = fmaxf(m, vals[i]);
    }
#pragma unroll
    for (int o = 16; o; o >>= 1) m = fmaxf(m, __shfl_xor_sync(0xffffffffu, m, o));
    if ((tid & 31) == 0) red[tid >> 5] = m;
    __syncthreads();
    float bm = red[0];
#pragma unroll
    for (int i = 1; i < 8; i++) bm = fmaxf(bm, red[i]);
    __syncthreads();

    float s = 0.f;
#pragma unroll
    for (int i = 0; i < 8; i++) {
        vals[i] = __expf(vals[i] - bm);
        s += vals[i];
    }
#pragma unroll
    for (int o = 16; o; o >>= 1) s += __shfl_xor_sync(0xffffffffu, s, o);
    if ((tid & 31) == 0) red[tid >> 5] = s;
    __syncthreads();
    float tot = 0.f;
#pragma unroll
    for (int i = 0; i < 8; i++) tot += red[i];
    float inv = 1.0f / tot;
#pragma unroll
    for (int i = 0; i < 8; i++)
        g_P[ro + tid + i * 256] = __float2half(vals[i] * inv);
}

// ================= Stage 4: O = P * V (single fp16) ============================
#define V_OFF_A  0
#define V_OFF_B  10240
#define V_STAGE  20480

__global__ __launch_bounds__(256, 2) void pv_kernel(float* __restrict__ out)
{
    const int z = blockIdx.z;
    const size_t so = (size_t)z * SEQ * SEQ;
    const size_t vo = (size_t)z * SEQ * CH;
    const int rowBlock = blockIdx.y * 128;
    const int colBlock = blockIdx.x * 128;

    const __nv_bfloat16* A = (const __nv_bfloat16*)(g_P + so);
    const __nv_bfloat16* B = (const __nv_bfloat16*)(g_Vh + vo);   // [k][n] MN-major

    const int tid  = threadIdx.x;
    const int lane = tid & 31;
    const int wid  = tid >> 5;
    const int warpRow = wid & 3;
    const int warpCol = wid >> 2;
    const uint32_t sbase = smem_u32(dsmem);

    float acc[2][8][4];
#pragma unroll
    for (int mt = 0; mt < 2; mt++)
#pragma unroll
        for (int nt = 0; nt < 8; nt++)
#pragma unroll
            for (int e = 0; e < 4; e++) acc[mt][nt][e] = 0.f;

    const uint32_t aOff  = ((warpRow * 32 + (lane & 15)) * LDA + ((lane >> 4) << 3)) * 2;
    const uint32_t bOffT = ((lane & 15) * LDBT + warpCol * 64 + ((lane >> 4) << 3)) * 2;

    const int ntiles = SEQ >> 5;    // 64

    ld_km(sbase + V_OFF_A, A, SEQ, rowBlock, 0, tid);
    ld_mn(sbase + V_OFF_B, B, CH, colBlock, 0, tid);
    CP_COMMIT();
    ld_km(sbase + V_STAGE + V_OFF_A, A, SEQ, rowBlock, 32, tid);
    ld_mn(sbase + V_STAGE + V_OFF_B, B, CH, colBlock, 32, tid);
    CP_COMMIT();

    for (int kt = 0; kt < ntiles; kt++) {
        if (kt + 1 < ntiles) { CP_WAIT1(); } else { CP_WAIT0(); }
        __syncthreads();

        const uint32_t sb = sbase + (kt & 1) * V_STAGE;
#pragma unroll
        for (int ks = 0; ks < 2; ks++) {
            const int kb = ks * 16;
            uint32_t ah[2][4];
#pragma unroll
            for (int mt = 0; mt < 2; mt++) {
                uint32_t ad = sb + V_OFF_A + aOff + (mt * 16 * LDA + kb) * 2;
                LDMATRIX_X4(ah[mt][0], ah[mt][1], ah[mt][2], ah[mt][3], ad);
            }
#pragma unroll
            for (int np = 0; np < 4; np++) {
                uint32_t bt[4];
                uint32_t bd = sb + V_OFF_B + bOffT + (kb * LDBT + np * 16) * 2;
                LDMATRIX_X4_T(bt[0], bt[1], bt[2], bt[3], bd);
#pragma unroll
                for (int half = 0; half < 2; half++) {
                    uint32_t b0 = bt[half * 2], b1 = bt[half * 2 + 1];
#pragma unroll
                    for (int mt = 0; mt < 2; mt++) {
                        int nt = np * 2 + half;
                        mma_fp16(acc[mt][nt], ah[mt][0], ah[mt][1], ah[mt][2], ah[mt][3], b0, b1);
                    }
                }
            }
        }
        __syncthreads();

        if (kt + 2 < ntiles) {
            const uint32_t sb2 = sbase + (kt & 1) * V_STAGE;
            const int k0 = (kt + 2) * 32;
            ld_km(sb2 + V_OFF_A, A, SEQ, rowBlock, k0, tid);
            ld_mn(sb2 + V_OFF_B, B, CH, colBlock, k0, tid);
            CP_COMMIT();
        }
    }

    float* O = out + vo;
#pragma unroll
    for (int mt = 0; mt < 2; mt++) {
#pragma unroll
        for (int nt = 0; nt < 8; nt++) {
            int row = rowBlock + warpRow * 32 + mt * 16 + (lane >> 2);
            int col = colBlock + warpCol * 64 + nt * 8 + (lane & 3) * 2;
            *(float2*)(O + (size_t)row * CH + col) =
                make_float2(acc[mt][nt][0], acc[mt][nt][1]);
            *(float2*)(O + (size_t)(row + 8) * CH + col) =
                make_float2(acc[mt][nt][2], acc[mt][nt][3]);
        }
    }
}

// ---------------------------------------------------------------------------
extern "C" void kernel_launch(void* const* d_in, const int* in_sizes, int n_in,
                              void* d_out, int out_size)
{
    const float* q  = (const float*)d_in[0];
    const float* k  = (const float*)d_in[1];
    const float* v  = (const float*)d_in[2];
    const float* Wq = (const float*)d_in[3];
    const float* bq = (const float*)d_in[4];
    const float* Wk = (const float*)d_in[5];
    const float* bk = (const float*)d_in[6];
    const float* Wv = (const float*)d_in[7];
    const float* bv = (const float*)d_in[8];
    float* out = (float*)d_out;

    static int configured = 0;
    if (!configured) {
        cudaFuncSetAttribute(proj_kernel, cudaFuncAttributeMaxDynamicSharedMemorySize, 2 * P_STAGE);
        cudaFuncSetAttribute(qk_kernel,   cudaFuncAttributeMaxDynamicSharedMemorySize, 2 * Q_STAGE);
        cudaFuncSetAttribute(pv_kernel,   cudaFuncAttributeMaxDynamicSharedMemorySize, 2 * V_STAGE);
        configured = 1;
    }

    dim3 gPre(8192, 1, 6);
    pre_kernel<<<gPre, 256>>>(q, k, v, Wq, Wk, Wv);

    dim3 gProj(CH / 128, ROWS / 128, 3);      // (4, 128, 3)
    proj_kernel<<<gProj, 256, 2 * P_STAGE>>>(bq, bk, bv);

    dim3 gQK(SEQ / 128, SEQ / 128, BATCH);    // (16, 16, 8)
    qk_kernel<<<gQK, 256, 2 * Q_STAGE>>>();

    softmax_kernel<<<ROWS, 256>>>();          // 16384 rows

    dim3 gPV(CH / 128, SEQ / 128, BATCH);     // (4, 16, 8)
    pv_kernel<<<gPV, 256, 2 * V_STAGE>>>(out);
}

// round 8
// speedup vs baseline: 1.6495x; 1.1269x over previous
#include <cuda_runtime.h>
#include <cuda_bf16.h>
#include <cuda_fp16.h>
#include <cstdint>

#define BATCH 8
#define SEQ   2048
#define CH    512
#define ROWS  (BATCH * SEQ)          // 16384
#define SCALE 0.25f
#define RC    ((size_t)ROWS * CH)    // 8388608
#define SS    ((size_t)BATCH * SEQ * SEQ)

// ---------------- persistent scratch ----------------
__device__ __nv_bfloat16 g_Ihi[3 * RC], g_Ilo[3 * RC];          // split inputs q,k,v (bf16)
__device__ __nv_bfloat16 g_Whi[3 * CH * CH], g_Wlo[3 * CH * CH];// split weights (bf16)
__device__ __half g_Qh[RC];             // Q projected, pre-scaled, single fp16
__device__ __half g_Kh[RC];             // K projected, single fp16
__device__ __half g_Vh[RC];             // V projected, single fp16
__device__ float  g_S[SS];              // raw scores fp32
__device__ __half g_P[SS];              // softmax probs, single fp16

// ---------------- smem pitches ----------------
#define LDA   40        // K-major pitch, elems (80 B rows)
#define LDBT  136       // trans-B pitch, elems (272 B rows)

extern __shared__ char dsmem[];

// ---------------- PTX helpers ----------------
__device__ __forceinline__ uint32_t smem_u32(const void* p) {
    uint32_t a;
    asm("{ .reg .u64 t; cvta.to.shared.u64 t, %1; cvt.u32.u64 %0, t; }"
        : "=r"(a) : "l"(p));
    return a;
}
__device__ __forceinline__ void cp16(uint32_t dst, const void* src) {
    asm volatile("cp.async.cg.shared.global [%0], [%1], 16;" :: "r"(dst), "l"(src));
}
#define CP_COMMIT() asm volatile("cp.async.commit_group;" ::: "memory")
#define CP_WAIT0()  asm volatile("cp.async.wait_group 0;" ::: "memory")
#define CP_WAIT1()  asm volatile("cp.async.wait_group 1;" ::: "memory")

#define LDMATRIX_X4(r0, r1, r2, r3, addr) \
    asm volatile("ldmatrix.sync.aligned.m8n8.x4.shared.b16 {%0,%1,%2,%3}, [%4];" \
                 : "=r"(r0), "=r"(r1), "=r"(r2), "=r"(r3) : "r"(addr))
#define LDMATRIX_X4_T(r0, r1, r2, r3, addr) \
    asm volatile("ldmatrix.sync.aligned.m8n8.x4.trans.shared.b16 {%0,%1,%2,%3}, [%4];" \
                 : "=r"(r0), "=r"(r1), "=r"(r2), "=r"(r3) : "r"(addr))

__device__ __forceinline__ void mma_bf16(float* c,
                                         uint32_t a0, uint32_t a1, uint32_t a2, uint32_t a3,
                                         uint32_t b0, uint32_t b1) {
    asm volatile(
        "mma.sync.aligned.m16n8k16.row.col.f32.bf16.bf16.f32 "
        "{%0,%1,%2,%3}, {%4,%5,%6,%7}, {%8,%9}, {%0,%1,%2,%3};"
        : "+f"(c[0]), "+f"(c[1]), "+f"(c[2]), "+f"(c[3])
        : "r"(a0), "r"(a1), "r"(a2), "r"(a3), "r"(b0), "r"(b1));
}
__device__ __forceinline__ void mma_fp16(float* c,
                                         uint32_t a0, uint32_t a1, uint32_t a2, uint32_t a3,
                                         uint32_t b0, uint32_t b1) {
    asm volatile(
        "mma.sync.aligned.m16n8k16.row.col.f32.f16.f16.f32 "
        "{%0,%1,%2,%3}, {%4,%5,%6,%7}, {%8,%9}, {%0,%1,%2,%3};"
        : "+f"(c[0]), "+f"(c[1]), "+f"(c[2]), "+f"(c[3])
        : "r"(a0), "r"(a1), "r"(a2), "r"(a3), "r"(b0), "r"(b1));
}

__device__ __forceinline__ void split2(float x, float y, uint32_t& hi, uint32_t& lo) {
    __nv_bfloat16 hx = __float2bfloat16(x);
    __nv_bfloat16 hy = __float2bfloat16(y);
    __nv_bfloat16 lx = __float2bfloat16(x - __bfloat162float(hx));
    __nv_bfloat16 ly = __float2bfloat16(y - __bfloat162float(hy));
    __nv_bfloat162 H = __halves2bfloat162(hx, hy);
    __nv_bfloat162 L = __halves2bfloat162(lx, ly);
    hi = *reinterpret_cast<uint32_t*>(&H);
    lo = *reinterpret_cast<uint32_t*>(&L);
}

// ---------------- tile loaders (cp.async, 16-bit element arrays) ----------------
// K-major [row][k] tile: 128 rows x 32 k, dst pitch 80B.
__device__ __forceinline__ void ld_km(uint32_t dst, const __nv_bfloat16* src,
                                      int ld, int rowBlock, int k0, int tid)
{
#pragma unroll
    for (int i = 0; i < 2; i++) {
        int c = i * 256 + tid;            // 512 chunks: 128 rows x 4
        int r = c >> 2, j = c & 3;
        cp16(dst + r * 80 + j * 16, src + (size_t)(rowBlock + r) * ld + k0 + j * 8);
    }
}
// MN-major [k][n] tile: 32 k-rows x 128 n, dst pitch 272B.
__device__ __forceinline__ void ld_mn(uint32_t dst, const __nv_bfloat16* src,
                                      int ld, int colBlock, int k0, int tid)
{
#pragma unroll
    for (int i = 0; i < 2; i++) {
        int c = i * 256 + tid;            // 512 chunks: 32 rows x 16
        int k = c >> 4, j = c & 15;
        cp16(dst + k * 272 + j * 16, src + (size_t)(k0 + k) * ld + colBlock + j * 8);
    }
}

// ================= proj core: bf16 3-term split (proven) =======================
#define P_OFF_AHI   0
#define P_OFF_ALO   10240
#define P_OFF_BHI   20480
#define P_OFF_BLO   30720
#define P_STAGE     40960

__device__ __forceinline__ void tc_core3(
    const __nv_bfloat16* __restrict__ Ahi, const __nv_bfloat16* __restrict__ Alo,
    const __nv_bfloat16* __restrict__ Bhi, const __nv_bfloat16* __restrict__ Blo,
    int K_total, int ldB, int rowBlock, int colBlock,
    float acc[2][8][4])
{
    const int tid  = threadIdx.x;
    const int lane = tid & 31;
    const int wid  = tid >> 5;
    const int warpRow = wid & 3;
    const int warpCol = wid >> 2;
    const uint32_t sbase = smem_u32(dsmem);

#pragma unroll
    for (int mt = 0; mt < 2; mt++)
#pragma unroll
        for (int nt = 0; nt < 8; nt++)
#pragma unroll
            for (int e = 0; e < 4; e++) acc[mt][nt][e] = 0.f;

    const uint32_t aOff = ((warpRow * 32 + (lane & 15)) * LDA + ((lane >> 4) << 3)) * 2;
    const uint32_t bOffT = ((lane & 15) * LDBT + warpCol * 64 + ((lane >> 4) << 3)) * 2;

    const int ntiles = K_total >> 5;

    ld_km(sbase + P_OFF_AHI, Ahi, K_total, rowBlock, 0, tid);
    ld_km(sbase + P_OFF_ALO, Alo, K_total, rowBlock, 0, tid);
    ld_mn(sbase + P_OFF_BHI, Bhi, ldB, colBlock, 0, tid);
    ld_mn(sbase + P_OFF_BLO, Blo, ldB, colBlock, 0, tid);
    CP_COMMIT();
    ld_km(sbase + P_STAGE + P_OFF_AHI, Ahi, K_total, rowBlock, 32, tid);
    ld_km(sbase + P_STAGE + P_OFF_ALO, Alo, K_total, rowBlock, 32, tid);
    ld_mn(sbase + P_STAGE + P_OFF_BHI, Bhi, ldB, colBlock, 32, tid);
    ld_mn(sbase + P_STAGE + P_OFF_BLO, Blo, ldB, colBlock, 32, tid);
    CP_COMMIT();

    for (int kt = 0; kt < ntiles; kt++) {
        if (kt + 1 < ntiles) { CP_WAIT1(); } else { CP_WAIT0(); }
        __syncthreads();

        const uint32_t sb = sbase + (kt & 1) * P_STAGE;
#pragma unroll
        for (int ks = 0; ks < 2; ks++) {
            const int kb = ks * 16;
            uint32_t ah[2][4], al[2][4];
            uint32_t bh[2][4], bl[2][4];
#pragma unroll
            for (int mt = 0; mt < 2; mt++) {
                uint32_t ad = sb + aOff + (mt * 16 * LDA + kb) * 2;
                LDMATRIX_X4(ah[mt][0], ah[mt][1], ah[mt][2], ah[mt][3], ad + P_OFF_AHI);
                LDMATRIX_X4(al[mt][0], al[mt][1], al[mt][2], al[mt][3], ad + P_OFF_ALO);
            }
            {
                uint32_t bd = sb + bOffT + (kb * LDBT) * 2;
                LDMATRIX_X4_T(bh[0][0], bh[0][1], bh[0][2], bh[0][3], bd + P_OFF_BHI);
                LDMATRIX_X4_T(bl[0][0], bl[0][1], bl[0][2], bl[0][3], bd + P_OFF_BLO);
            }
#pragma unroll
            for (int np = 0; np < 4; np++) {
                const int cur = np & 1;
                const int nxt = cur ^ 1;
                if (np < 3) {
                    uint32_t bd = sb + bOffT + (kb * LDBT + (np + 1) * 16) * 2;
                    LDMATRIX_X4_T(bh[nxt][0], bh[nxt][1], bh[nxt][2], bh[nxt][3], bd + P_OFF_BHI);
                    LDMATRIX_X4_T(bl[nxt][0], bl[nxt][1], bl[nxt][2], bl[nxt][3], bd + P_OFF_BLO);
                }
#pragma unroll
                for (int half = 0; half < 2; half++) {
                    uint32_t bh0 = bh[cur][half * 2], bh1 = bh[cur][half * 2 + 1];
                    uint32_t bl0 = bl[cur][half * 2], bl1 = bl[cur][half * 2 + 1];
#pragma unroll
                    for (int mt = 0; mt < 2; mt++) {
                        int nt = np * 2 + half;
                        mma_bf16(acc[mt][nt], ah[mt][0], ah[mt][1], ah[mt][2], ah[mt][3], bh0, bh1);
                        mma_bf16(acc[mt][nt], ah[mt][0], ah[mt][1], ah[mt][2], ah[mt][3], bl0, bl1);
                        mma_bf16(acc[mt][nt], al[mt][0], al[mt][1], al[mt][2], al[mt][3], bh0, bh1);
                    }
                }
            }
        }
        __syncthreads();

        if (kt + 2 < ntiles) {
            const uint32_t sb2 = sbase + (kt & 1) * P_STAGE;
            const int k0 = (kt + 2) * 32;
            ld_km(sb2 + P_OFF_AHI, Ahi, K_total, rowBlock, k0, tid);
            ld_km(sb2 + P_OFF_ALO, Alo, K_total, rowBlock, k0, tid);
            ld_mn(sb2 + P_OFF_BHI, Bhi, ldB, colBlock, k0, tid);
            ld_mn(sb2 + P_OFF_BLO, Blo, ldB, colBlock, k0, tid);
            CP_COMMIT();
        }
    }
}

// ================= Stage 0: split inputs + weights to bf16 hi/lo ===============
__global__ __launch_bounds__(256) void pre_kernel(
    const float* __restrict__ q, const float* __restrict__ k, const float* __restrict__ v,
    const float* __restrict__ Wq, const float* __restrict__ Wk, const float* __restrict__ Wv)
{
    const int z = blockIdx.z;
    const float* src;
    __nv_bfloat16 *hi, *lo;
    size_t n4;
    if (z < 3) {
        src = (z == 0) ? q : (z == 1) ? k : v;
        hi = g_Ihi + (size_t)z * RC; lo = g_Ilo + (size_t)z * RC;
        n4 = RC / 4;
    } else {
        int w = z - 3;
        src = (w == 0) ? Wq : (w == 1) ? Wk : Wv;
        hi = g_Whi + (size_t)w * CH * CH; lo = g_Wlo + (size_t)w * CH * CH;
        n4 = (size_t)CH * CH / 4;
    }
    size_t i4 = (size_t)blockIdx.x * 256 + threadIdx.x;
    if (i4 >= n4) return;
    float4 val = ((const float4*)src)[i4];
    uint32_t h01, l01, h23, l23;
    split2(val.x, val.y, h01, l01);
    split2(val.z, val.w, h23, l23);
    *(uint2*)(hi + i4 * 4) = make_uint2(h01, h23);
    *(uint2*)(lo + i4 * 4) = make_uint2(l01, l23);
}

// ================= Stage 1: projections ========================================
// All outputs single fp16; Q pre-scaled by 0.25.
__global__ __launch_bounds__(256, 2) void proj_kernel(
    const float* __restrict__ bq, const float* __restrict__ bk, const float* __restrict__ bv)
{
    const int z = blockIdx.z;
    const __nv_bfloat16* Ahi = g_Ihi + (size_t)z * RC;
    const __nv_bfloat16* Alo = g_Ilo + (size_t)z * RC;
    const __nv_bfloat16* Bhi = g_Whi + (size_t)z * CH * CH;
    const __nv_bfloat16* Blo = g_Wlo + (size_t)z * CH * CH;
    const float* bias = (z == 0) ? bq : (z == 1) ? bk : bv;
    __half* dst = (z == 0) ? g_Qh : (z == 1) ? g_Kh : g_Vh;
    const float alpha = (z == 0) ? SCALE : 1.0f;

    const int rowBlock = blockIdx.y * 128;
    const int colBlock = blockIdx.x * 128;

    float acc[2][8][4];
    tc_core3(Ahi, Alo, Bhi, Blo, CH, CH, rowBlock, colBlock, acc);

    const int lane = threadIdx.x & 31;
    const int wid  = threadIdx.x >> 5;
    const int warpRow = wid & 3, warpCol = wid >> 2;
#pragma unroll
    for (int mt = 0; mt < 2; mt++) {
#pragma unroll
        for (int nt = 0; nt < 8; nt++) {
            int row = rowBlock + warpRow * 32 + mt * 16 + (lane >> 2);
            int col = colBlock + warpCol * 64 + nt * 8 + (lane & 3) * 2;
            float2 b = *(const float2*)(bias + col);
            float x0 = (acc[mt][nt][0] + b.x) * alpha;
            float y0 = (acc[mt][nt][1] + b.y) * alpha;
            float x1 = (acc[mt][nt][2] + b.x) * alpha;
            float y1 = (acc[mt][nt][3] + b.y) * alpha;
            size_t o0 = (size_t)row * CH + col;
            size_t o1 = (size_t)(row + 8) * CH + col;
            *(__half2*)(dst + o0) = __halves2half2(__float2half(x0), __float2half(y0));
            *(__half2*)(dst + o1) = __halves2half2(__float2half(x1), __float2half(y1));
        }
    }
}

// ================= Stage 2: S = Q*K^T (single-term fp16) =======================
#define Q_OFF_A  0
#define Q_OFF_B  10240
#define Q_STAGE  20480

__global__ __launch_bounds__(256, 2) void qk_kernel()
{
    const int z = blockIdx.z;
    const size_t po = (size_t)z * SEQ * CH;
    float* S = g_S + (size_t)z * SEQ * SEQ;
    const int rowBlock = blockIdx.y * 128;
    const int colBlock = blockIdx.x * 128;

    const __nv_bfloat16* A = (const __nv_bfloat16*)(g_Qh + po);
    const __nv_bfloat16* B = (const __nv_bfloat16*)(g_Kh + po);

    const int tid  = threadIdx.x;
    const int lane = tid & 31;
    const int wid  = tid >> 5;
    const int warpRow = wid & 3;
    const int warpCol = wid >> 2;
    const uint32_t sbase = smem_u32(dsmem);

    float acc[2][8][4];
#pragma unroll
    for (int mt = 0; mt < 2; mt++)
#pragma unroll
        for (int nt = 0; nt < 8; nt++)
#pragma unroll
            for (int e = 0; e < 4; e++) acc[mt][nt][e] = 0.f;

    const uint32_t aOff = ((warpRow * 32 + (lane & 15)) * LDA + ((lane >> 4) << 3)) * 2;
    const uint32_t bOff = ((warpCol * 64 + ((lane >> 4) << 3) + (lane & 7)) * LDA
                          + (((lane >> 3) & 1) << 3)) * 2;

    const int ntiles = CH >> 5;    // 16

    ld_km(sbase + Q_OFF_A, A, CH, rowBlock, 0, tid);
    ld_km(sbase + Q_OFF_B, B, CH, colBlock, 0, tid);
    CP_COMMIT();
    ld_km(sbase + Q_STAGE + Q_OFF_A, A, CH, rowBlock, 32, tid);
    ld_km(sbase + Q_STAGE + Q_OFF_B, B, CH, colBlock, 32, tid);
    CP_COMMIT();

    for (int kt = 0; kt < ntiles; kt++) {
        if (kt + 1 < ntiles) { CP_WAIT1(); } else { CP_WAIT0(); }
        __syncthreads();

        const uint32_t sb = sbase + (kt & 1) * Q_STAGE;
#pragma unroll
        for (int ks = 0; ks < 2; ks++) {
            const int kb = ks * 16;
            uint32_t ah[2][4];
#pragma unroll
            for (int mt = 0; mt < 2; mt++) {
                uint32_t ad = sb + Q_OFF_A + aOff + (mt * 16 * LDA + kb) * 2;
                LDMATRIX_X4(ah[mt][0], ah[mt][1], ah[mt][2], ah[mt][3], ad);
            }
#pragma unroll
            for (int np = 0; np < 4; np++) {
                uint32_t bh[4];
                uint32_t bd = sb + Q_OFF_B + bOff + (np * 16 * LDA + kb) * 2;
                LDMATRIX_X4(bh[0], bh[1], bh[2], bh[3], bd);
#pragma unroll
                for (int half = 0; half < 2; half++) {
                    uint32_t b0 = bh[half * 2], b1 = bh[half * 2 + 1];
#pragma unroll
                    for (int mt = 0; mt < 2; mt++) {
                        int nt = np * 2 + half;
                        mma_fp16(acc[mt][nt], ah[mt][0], ah[mt][1], ah[mt][2], ah[mt][3], b0, b1);
                    }
                }
            }
        }
        __syncthreads();

        if (kt + 2 < ntiles) {
            const uint32_t sb2 = sbase + (kt & 1) * Q_STAGE;
            const int k0 = (kt + 2) * 32;
            ld_km(sb2 + Q_OFF_A, A, CH, rowBlock, k0, tid);
            ld_km(sb2 + Q_OFF_B, B, CH, colBlock, k0, tid);
            CP_COMMIT();
        }
    }

#pragma unroll
    for (int mt = 0; mt < 2; mt++) {
#pragma unroll
        for (int nt = 0; nt < 8; nt++) {
            int row = rowBlock + warpRow * 32 + mt * 16 + (lane >> 2);
            int col = colBlock + warpCol * 64 + nt * 8 + (lane & 3) * 2;
            *(float2*)(S + (size_t)row * SEQ + col) =
                make_float2(acc[mt][nt][0], acc[mt][nt][1]);
            *(float2*)(S + (size_t)(row + 8) * SEQ + col) =
                make_float2(acc[mt][nt][2], acc[mt][nt][3]);
        }
    }
}

// ================= Stage 3: softmax -> single fp16 probs =======================
__global__ __launch_bounds__(256) void softmax_kernel()
{
    __shared__ float red[8];
    const size_t ro = (size_t)blockIdx.x * SEQ;
    const float* row = g_S + ro;
    const int tid = threadIdx.x;

    float vals[8];
    float m = -3.0e38f;
#pragma unroll
    for (int i = 0; i < 8; i++) {
        vals[i] = row[tid + i * 256];
        m = fmaxf(m, vals[i]);
    }
#pragma unroll
    for (int o = 16; o; o >>= 1) m = fmaxf(m, __shfl_xor_sync(0xffffffffu, m, o));
    if ((tid & 31) == 0) red[tid >> 5] = m;
    __syncthreads();
    float bm = red[0];
#pragma unroll
    for (int i = 1; i < 8; i++) bm = fmaxf(bm, red[i]);
    __syncthreads();

    float s = 0.f;
#pragma unroll
    for (int i = 0; i < 8; i++) {
        vals[i] = __expf(vals[i] - bm);
        s += vals[i];
    }
#pragma unroll
    for (int o = 16; o; o >>= 1) s += __shfl_xor_sync(0xffffffffu, s, o);
    if ((tid & 31) == 0) red[tid >> 5] = s;
    __syncthreads();
    float tot = 0.f;
#pragma unroll
    for (int i = 0; i < 8; i++) tot += red[i];
    float inv = 1.0f / tot;
#pragma unroll
    for (int i = 0; i < 8; i++)
        g_P[ro + tid + i * 256] = __float2half(vals[i] * inv);
}

// ================= Stage 4: O = P * V (single fp16) ============================
#define V_OFF_A  0
#define V_OFF_B  10240
#define V_STAGE  20480

__global__ __launch_bounds__(256, 2) void pv_kernel(float* __restrict__ out)
{
    const int z = blockIdx.z;
    const size_t so = (size_t)z * SEQ * SEQ;
    const size_t vo = (size_t)z * SEQ * CH;
    const int rowBlock = blockIdx.y * 128;
    const int colBlock = blockIdx.x * 128;

    const __nv_bfloat16* A = (const __nv_bfloat16*)(g_P + so);
    const __nv_bfloat16* B = (const __nv_bfloat16*)(g_Vh + vo);   // [k][n] MN-major

    const int tid  = threadIdx.x;
    const int lane = tid & 31;
    const int wid  = tid >> 5;
    const int warpRow = wid & 3;
    const int warpCol = wid >> 2;
    const uint32_t sbase = smem_u32(dsmem);

    float acc[2][8][4];
#pragma unroll
    for (int mt = 0; mt < 2; mt++)
#pragma unroll
        for (int nt = 0; nt < 8; nt++)
#pragma unroll
            for (int e = 0; e < 4; e++) acc[mt][nt][e] = 0.f;

    const uint32_t aOff  = ((warpRow * 32 + (lane & 15)) * LDA + ((lane >> 4) << 3)) * 2;
    const uint32_t bOffT = ((lane & 15) * LDBT + warpCol * 64 + ((lane >> 4) << 3)) * 2;

    const int ntiles = SEQ >> 5;    // 64

    ld_km(sbase + V_OFF_A, A, SEQ, rowBlock, 0, tid);
    ld_mn(sbase + V_OFF_B, B, CH, colBlock, 0, tid);
    CP_COMMIT();
    ld_km(sbase + V_STAGE + V_OFF_A, A, SEQ, rowBlock, 32, tid);
    ld_mn(sbase + V_STAGE + V_OFF_B, B, CH, colBlock, 32, tid);
    CP_COMMIT();

    for (int kt = 0; kt < ntiles; kt++) {
        if (kt + 1 < ntiles) { CP_WAIT1(); } else { CP_WAIT0(); }
        __syncthreads();

        const uint32_t sb = sbase + (kt & 1) * V_STAGE;
#pragma unroll
        for (int ks = 0; ks < 2; ks++) {
            const int kb = ks * 16;
            uint32_t ah[2][4];
#pragma unroll
            for (int mt = 0; mt < 2; mt++) {
                uint32_t ad = sb + V_OFF_A + aOff + (mt * 16 * LDA + kb) * 2;
                LDMATRIX_X4(ah[mt][0], ah[mt][1], ah[mt][2], ah[mt][3], ad);
            }
#pragma unroll
            for (int np = 0; np < 4; np++) {
                uint32_t bt[4];
                uint32_t bd = sb + V_OFF_B + bOffT + (kb * LDBT + np * 16) * 2;
                LDMATRIX_X4_T(bt[0], bt[1], bt[2], bt[3], bd);
#pragma unroll
                for (int half = 0; half < 2; half++) {
                    uint32_t b0 = bt[half * 2], b1 = bt[half * 2 + 1];
#pragma unroll
                    for (int mt = 0; mt < 2; mt++) {
                        int nt = np * 2 + half;
                        mma_fp16(acc[mt][nt], ah[mt][0], ah[mt][1], ah[mt][2], ah[mt][3], b0, b1);
                    }
                }
            }
        }
        __syncthreads();

        if (kt + 2 < ntiles) {
            const uint32_t sb2 = sbase + (kt & 1) * V_STAGE;
            const int k0 = (kt + 2) * 32;
            ld_km(sb2 + V_OFF_A, A, SEQ, rowBlock, k0, tid);
            ld_mn(sb2 + V_OFF_B, B, CH, colBlock, k0, tid);
            CP_COMMIT();
        }
    }

    float* O = out + vo;
#pragma unroll
    for (int mt = 0; mt < 2; mt++) {
#pragma unroll
        for (int nt = 0; nt < 8; nt++) {
            int row = rowBlock + warpRow * 32 + mt * 16 + (lane >> 2);
            int col = colBlock + warpCol * 64 + nt * 8 + (lane & 3) * 2;
            *(float2*)(O + (size_t)row * CH + col) =
                make_float2(acc[mt][nt][0], acc[mt][nt][1]);
            *(float2*)(O + (size_t)(row + 8) * CH + col) =
                make_float2(acc[mt][nt][2], acc[mt][nt][3]);
        }
    }
}

// ---------------------------------------------------------------------------
extern "C" void kernel_launch(void* const* d_in, const int* in_sizes, int n_in,
                              void* d_out, int out_size)
{
    const float* q  = (const float*)d_in[0];
    const float* k  = (const float*)d_in[1];
    const float* v  = (const float*)d_in[2];
    const float* Wq = (const float*)d_in[3];
    const float* bq = (const float*)d_in[4];
    const float* Wk = (const float*)d_in[5];
    const float* bk = (const float*)d_in[6];
    const float* Wv = (const float*)d_in[7];
    const float* bv = (const float*)d_in[8];
    float* out = (float*)d_out;

    static int configured = 0;
    if (!configured) {
        cudaFuncSetAttribute(proj_kernel, cudaFuncAttributeMaxDynamicSharedMemorySize, 2 * P_STAGE);
        cudaFuncSetAttribute(qk_kernel,   cudaFuncAttributeMaxDynamicSharedMemorySize, 2 * Q_STAGE);
        cudaFuncSetAttribute(pv_kernel,   cudaFuncAttributeMaxDynamicSharedMemorySize, 2 * V_STAGE);
        configured = 1;
    }

    dim3 gPre(8192, 1, 6);
    pre_kernel<<<gPre, 256>>>(q, k, v, Wq, Wk, Wv);

    dim3 gProj(CH / 128, ROWS / 128, 3);      // (4, 128, 3)
    proj_kernel<<<gProj, 256, 2 * P_STAGE>>>(bq, bk, bv);

    dim3 gQK(SEQ / 128, SEQ / 128, BATCH);    // (16, 16, 8)
    qk_kernel<<<gQK, 256, 2 * Q_STAGE>>>();

    softmax_kernel<<<ROWS, 256>>>();          // 16384 rows

    dim3 gPV(CH / 128, SEQ / 128, BATCH);     // (4, 16, 8)
    pv_kernel<<<gPV, 256, 2 * V_STAGE>>>(out);
}

// round 10
// speedup vs baseline: 1.8594x; 1.1273x over previous
#include <cuda_runtime.h>
#include <cuda_bf16.h>
#include <cuda_fp16.h>
#include <cstdint>

#define BATCH 8
#define SEQ   2048
#define CH    512
#define ROWS  (BATCH * SEQ)          // 16384
#define SCALE 0.25f
#define RC    ((size_t)ROWS * CH)    // 8388608
#define SS    ((size_t)BATCH * SEQ * SEQ)

// ---------------- persistent scratch ----------------
__device__ __half g_Ihf[3 * RC], g_Ilf[3 * RC];   // inputs q,k,v split fp16 hi/lo
__device__ __half g_Wf[3 * CH * CH];              // weights single fp16
__device__ __half g_Qh[RC];             // Q projected, pre-scaled, fp16
__device__ __half g_Kh[RC];             // K projected, fp16
__device__ __half g_Vh[RC];             // V projected, fp16
__device__ float  g_S[SS];              // raw scores fp32
__device__ __half g_P[SS];              // softmax probs, fp16

// ---------------- smem pitches ----------------
#define LDA   40        // K-major pitch, elems (80 B rows)
#define LDBT  136       // trans-B pitch, elems (272 B rows)

extern __shared__ char dsmem[];

// ---------------- PTX helpers ----------------
__device__ __forceinline__ uint32_t smem_u32(const void* p) {
    uint32_t a;
    asm("{ .reg .u64 t; cvta.to.shared.u64 t, %1; cvt.u32.u64 %0, t; }"
        : "=r"(a) : "l"(p));
    return a;
}
__device__ __forceinline__ void cp16(uint32_t dst, const void* src) {
    asm volatile("cp.async.cg.shared.global [%0], [%1], 16;" :: "r"(dst), "l"(src));
}
#define CP_COMMIT() asm volatile("cp.async.commit_group;" ::: "memory")
#define CP_WAIT0()  asm volatile("cp.async.wait_group 0;" ::: "memory")
#define CP_WAIT1()  asm volatile("cp.async.wait_group 1;" ::: "memory")

#define LDMATRIX_X4(r0, r1, r2, r3, addr) \
    asm volatile("ldmatrix.sync.aligned.m8n8.x4.shared.b16 {%0,%1,%2,%3}, [%4];" \
                 : "=r"(r0), "=r"(r1), "=r"(r2), "=r"(r3) : "r"(addr))
#define LDMATRIX_X4_T(r0, r1, r2, r3, addr) \
    asm volatile("ldmatrix.sync.aligned.m8n8.x4.trans.shared.b16 {%0,%1,%2,%3}, [%4];" \
                 : "=r"(r0), "=r"(r1), "=r"(r2), "=r"(r3) : "r"(addr))

__device__ __forceinline__ void mma_fp16(float* c,
                                         uint32_t a0, uint32_t a1, uint32_t a2, uint32_t a3,
                                         uint32_t b0, uint32_t b1) {
    asm volatile(
        "mma.sync.aligned.m16n8k16.row.col.f32.f16.f16.f32 "
        "{%0,%1,%2,%3}, {%4,%5,%6,%7}, {%8,%9}, {%0,%1,%2,%3};"
        : "+f"(c[0]), "+f"(c[1]), "+f"(c[2]), "+f"(c[3])
        : "r"(a0), "r"(a1), "r"(a2), "r"(a3), "r"(b0), "r"(b1));
}

__device__ __forceinline__ void split2h(float x, float y, uint32_t& hi, uint32_t& lo) {
    __half hx = __float2half(x);
    __half hy = __float2half(y);
    __half lx = __float2half(x - __half2float(hx));
    __half ly = __float2half(y - __half2float(hy));
    __half2 H = __halves2half2(hx, hy);
    __half2 L = __halves2half2(lx, ly);
    hi = *reinterpret_cast<uint32_t*>(&H);
    lo = *reinterpret_cast<uint32_t*>(&L);
}

// ---------------- tile loaders (cp.async, 16-bit element arrays) ----------------
// K-major [row][k] tile: 128 rows x 32 k, dst pitch 80B.
__device__ __forceinline__ void ld_km(uint32_t dst, const __half* src,
                                      int ld, int rowBlock, int k0, int tid)
{
#pragma unroll
    for (int i = 0; i < 2; i++) {
        int c = i * 256 + tid;            // 512 chunks: 128 rows x 4
        int r = c >> 2, j = c & 3;
        cp16(dst + r * 80 + j * 16, src + (size_t)(rowBlock + r) * ld + k0 + j * 8);
    }
}
// MN-major [k][n] tile: 32 k-rows x 128 n, dst pitch 272B.
__device__ __forceinline__ void ld_mn(uint32_t dst, const __half* src,
                                      int ld, int colBlock, int k0, int tid)
{
#pragma unroll
    for (int i = 0; i < 2; i++) {
        int c = i * 256 + tid;            // 512 chunks: 32 rows x 16
        int k = c >> 4, j = c & 15;
        cp16(dst + k * 272 + j * 16, src + (size_t)(k0 + k) * ld + colBlock + j * 8);
    }
}

// ================= Stage 0: inputs -> fp16 hi/lo, weights -> fp16 ==============
__global__ __launch_bounds__(256) void pre_kernel(
    const float* __restrict__ q, const float* __restrict__ k, const float* __restrict__ v,
    const float* __restrict__ Wq, const float* __restrict__ Wk, const float* __restrict__ Wv)
{
    const int z = blockIdx.z;
    if (z < 3) {
        const float* src = (z == 0) ? q : (z == 1) ? k : v;
        __half* hi = g_Ihf + (size_t)z * RC;
        __half* lo = g_Ilf + (size_t)z * RC;
        size_t i4 = (size_t)blockIdx.x * 256 + threadIdx.x;
        if (i4 >= RC / 4) return;
        float4 val = ((const float4*)src)[i4];
        uint32_t h01, l01, h23, l23;
        split2h(val.x, val.y, h01, l01);
        split2h(val.z, val.w, h23, l23);
        *(uint2*)(hi + i4 * 4) = make_uint2(h01, h23);
        *(uint2*)(lo + i4 * 4) = make_uint2(l01, l23);
    } else {
        const int w = z - 3;
        const float* src = (w == 0) ? Wq : (w == 1) ? Wk : Wv;
        __half* dst = g_Wf + (size_t)w * CH * CH;
        size_t i4 = (size_t)blockIdx.x * 256 + threadIdx.x;
        if (i4 >= (size_t)CH * CH / 4) return;
        float4 val = ((const float4*)src)[i4];
        __half2 p0 = __halves2half2(__float2half(val.x), __float2half(val.y));
        __half2 p1 = __halves2half2(__float2half(val.z), __float2half(val.w));
        uint2 o;
        o.x = *reinterpret_cast<uint32_t*>(&p0);
        o.y = *reinterpret_cast<uint32_t*>(&p1);
        *(uint2*)(dst + i4 * 4) = o;
    }
}

// ================= Stage 1: projections (fp16 2-term: Ihi,Ilo x W) =============
// smem/stage: A_hi (10240) + A_lo (10240) + W trans tile (8704, padded)
#define P_OFF_AH 0
#define P_OFF_AL 10240
#define P_OFF_B  20480
#define P_STAGE  30720

__global__ __launch_bounds__(256, 2) void proj_kernel(
    const float* __restrict__ bq, const float* __restrict__ bk, const float* __restrict__ bv)
{
    const int z = blockIdx.z;
    const __half* Ah = g_Ihf + (size_t)z * RC;
    const __half* Al = g_Ilf + (size_t)z * RC;
    const __half* B  = g_Wf + (size_t)z * CH * CH;   // [k][n] MN-major
    const float* bias = (z == 0) ? bq : (z == 1) ? bk : bv;
    __half* dst = (z == 0) ? g_Qh : (z == 1) ? g_Kh : g_Vh;
    const float alpha = (z == 0) ? SCALE : 1.0f;

    const int rowBlock = blockIdx.y * 128;
    const int colBlock = blockIdx.x * 128;

    const int tid  = threadIdx.x;
    const int lane = tid & 31;
    const int wid  = tid >> 5;
    const int warpRow = wid & 3;
    const int warpCol = wid >> 2;
    const uint32_t sbase = smem_u32(dsmem);

    float acc[2][8][4];
#pragma unroll
    for (int mt = 0; mt < 2; mt++)
#pragma unroll
        for (int nt = 0; nt < 8; nt++)
#pragma unroll
            for (int e = 0; e < 4; e++) acc[mt][nt][e] = 0.f;

    const uint32_t aOff  = ((warpRow * 32 + (lane & 15)) * LDA + ((lane >> 4) << 3)) * 2;
    const uint32_t bOffT = ((lane & 15) * LDBT + warpCol * 64 + ((lane >> 4) << 3)) * 2;

    const int ntiles = CH >> 5;    // 16

    ld_km(sbase + P_OFF_AH, Ah, CH, rowBlock, 0, tid);
    ld_km(sbase + P_OFF_AL, Al, CH, rowBlock, 0, tid);
    ld_mn(sbase + P_OFF_B,  B,  CH, colBlock, 0, tid);
    CP_COMMIT();
    ld_km(sbase + P_STAGE + P_OFF_AH, Ah, CH, rowBlock, 32, tid);
    ld_km(sbase + P_STAGE + P_OFF_AL, Al, CH, rowBlock, 32, tid);
    ld_mn(sbase + P_STAGE + P_OFF_B,  B,  CH, colBlock, 32, tid);
    CP_COMMIT();

    for (int kt = 0; kt < ntiles; kt++) {
        if (kt + 1 < ntiles) { CP_WAIT1(); } else { CP_WAIT0(); }
        __syncthreads();

        const uint32_t sb = sbase + (kt & 1) * P_STAGE;
#pragma unroll
        for (int ks = 0; ks < 2; ks++) {
            const int kb = ks * 16;
            uint32_t ah[2][4], al[2][4];
#pragma unroll
            for (int mt = 0; mt < 2; mt++) {
                uint32_t ad = sb + aOff + (mt * 16 * LDA + kb) * 2;
                LDMATRIX_X4(ah[mt][0], ah[mt][1], ah[mt][2], ah[mt][3], ad + P_OFF_AH);
                LDMATRIX_X4(al[mt][0], al[mt][1], al[mt][2], al[mt][3], ad + P_OFF_AL);
            }
#pragma unroll
            for (int np = 0; np < 4; np++) {
                uint32_t bt[4];
                uint32_t bd = sb + P_OFF_B + bOffT + (kb * LDBT + np * 16) * 2;
                LDMATRIX_X4_T(bt[0], bt[1], bt[2], bt[3], bd);
#pragma unroll
                for (int half = 0; half < 2; half++) {
                    uint32_t b0 = bt[half * 2], b1 = bt[half * 2 + 1];
#pragma unroll
                    for (int mt = 0; mt < 2; mt++) {
                        int nt = np * 2 + half;
                        mma_fp16(acc[mt][nt], ah[mt][0], ah[mt][1], ah[mt][2], ah[mt][3], b0, b1);
                        mma_fp16(acc[mt][nt], al[mt][0], al[mt][1], al[mt][2], al[mt][3], b0, b1);
                    }
                }
            }
        }
        __syncthreads();

        if (kt + 2 < ntiles) {
            const uint32_t sb2 = sbase + (kt & 1) * P_STAGE;
            const int k0 = (kt + 2) * 32;
            ld_km(sb2 + P_OFF_AH, Ah, CH, rowBlock, k0, tid);
            ld_km(sb2 + P_OFF_AL, Al, CH, rowBlock, k0, tid);
            ld_mn(sb2 + P_OFF_B,  B,  CH, colBlock, k0, tid);
            CP_COMMIT();
        }
    }

#pragma unroll
    for (int mt = 0; mt < 2; mt++) {
#pragma unroll
        for (int nt = 0; nt < 8; nt++) {
            int row = rowBlock + warpRow * 32 + mt * 16 + (lane >> 2);
            int col = colBlock + warpCol * 64 + nt * 8 + (lane & 3) * 2;
            float2 b = *(const float2*)(bias + col);
            float x0 = (acc[mt][nt][0] + b.x) * alpha;
            float y0 = (acc[mt][nt][1] + b.y) * alpha;
            float x1 = (acc[mt][nt][2] + b.x) * alpha;
            float y1 = (acc[mt][nt][3] + b.y) * alpha;
            size_t o0 = (size_t)row * CH + col;
            size_t o1 = (size_t)(row + 8) * CH + col;
            *(__half2*)(dst + o0) = __halves2half2(__float2half(x0), __float2half(y0));
            *(__half2*)(dst + o1) = __halves2half2(__float2half(x1), __float2half(y1));
        }
    }
}

// ================= Stage 2: S = Q*K^T (single-term fp16) =======================
#define Q_OFF_A  0
#define Q_OFF_B  10240
#define Q_STAGE  20480

__global__ __launch_bounds__(256, 2) void qk_kernel()
{
    const int z = blockIdx.z;
    const size_t po = (size_t)z * SEQ * CH;
    float* S = g_S + (size_t)z * SEQ * SEQ;
    const int rowBlock = blockIdx.y * 128;
    const int colBlock = blockIdx.x * 128;

    const __half* A = g_Qh + po;
    const __half* B = g_Kh + po;

    const int tid  = threadIdx.x;
    const int lane = tid & 31;
    const int wid  = tid >> 5;
    const int warpRow = wid & 3;
    const int warpCol = wid >> 2;
    const uint32_t sbase = smem_u32(dsmem);

    float acc[2][8][4];
#pragma unroll
    for (int mt = 0; mt < 2; mt++)
#pragma unroll
        for (int nt = 0; nt < 8; nt++)
#pragma unroll
            for (int e = 0; e < 4; e++) acc[mt][nt][e] = 0.f;

    const uint32_t aOff = ((warpRow * 32 + (lane & 15)) * LDA + ((lane >> 4) << 3)) * 2;
    const uint32_t bOff = ((warpCol * 64 + ((lane >> 4) << 3) + (lane & 7)) * LDA
                          + (((lane >> 3) & 1) << 3)) * 2;

    const int ntiles = CH >> 5;    // 16

    ld_km(sbase + Q_OFF_A, A, CH, rowBlock, 0, tid);
    ld_km(sbase + Q_OFF_B, B, CH, colBlock, 0, tid);
    CP_COMMIT();
    ld_km(sbase + Q_STAGE + Q_OFF_A, A, CH, rowBlock, 32, tid);
    ld_km(sbase + Q_STAGE + Q_OFF_B, B, CH, colBlock, 32, tid);
    CP_COMMIT();

    for (int kt = 0; kt < ntiles; kt++) {
        if (kt + 1 < ntiles) { CP_WAIT1(); } else { CP_WAIT0(); }
        __syncthreads();

        const uint32_t sb = sbase + (kt & 1) * Q_STAGE;
#pragma unroll
        for (int ks = 0; ks < 2; ks++) {
            const int kb = ks * 16;
            uint32_t ah[2][4];
#pragma unroll
            for (int mt = 0; mt < 2; mt++) {
                uint32_t ad = sb + Q_OFF_A + aOff + (mt * 16 * LDA + kb) * 2;
                LDMATRIX_X4(ah[mt][0], ah[mt][1], ah[mt][2], ah[mt][3], ad);
            }
#pragma unroll
            for (int np = 0; np < 4; np++) {
                uint32_t bh[4];
                uint32_t bd = sb + Q_OFF_B + bOff + (np * 16 * LDA + kb) * 2;
                LDMATRIX_X4(bh[0], bh[1], bh[2], bh[3], bd);
#pragma unroll
                for (int half = 0; half < 2; half++) {
                    uint32_t b0 = bh[half * 2], b1 = bh[half * 2 + 1];
#pragma unroll
                    for (int mt = 0; mt < 2; mt++) {
                        int nt = np * 2 + half;
                        mma_fp16(acc[mt][nt], ah[mt][0], ah[mt][1], ah[mt][2], ah[mt][3], b0, b1);
                    }
                }
            }
        }
        __syncthreads();

        if (kt + 2 < ntiles) {
            const uint32_t sb2 = sbase + (kt & 1) * Q_STAGE;
            const int k0 = (kt + 2) * 32;
            ld_km(sb2 + Q_OFF_A, A, CH, rowBlock, k0, tid);
            ld_km(sb2 + Q_OFF_B, B, CH, colBlock, k0, tid);
            CP_COMMIT();
        }
    }

#pragma unroll
    for (int mt = 0; mt < 2; mt++) {
#pragma unroll
        for (int nt = 0; nt < 8; nt++) {
            int row = rowBlock + warpRow * 32 + mt * 16 + (lane >> 2);
            int col = colBlock + warpCol * 64 + nt * 8 + (lane & 3) * 2;
            *(float2*)(S + (size_t)row * SEQ + col) =
                make_float2(acc[mt][nt][0], acc[mt][nt][1]);
            *(float2*)(S + (size_t)(row + 8) * SEQ + col) =
                make_float2(acc[mt][nt][2], acc[mt][nt][3]);
        }
    }
}

// ================= Stage 3: softmax -> single fp16 probs =======================
__global__ __launch_bounds__(256) void softmax_kernel()
{
    __shared__ float red[8];
    const size_t ro = (size_t)blockIdx.x * SEQ;
    const float* row = g_S + ro;
    const int tid = threadIdx.x;

    float vals[8];
    float m = -3.0e38f;
#pragma unroll
    for (int i = 0; i < 8; i++) {
        vals[i] = row[tid + i * 256];
        m = fmaxf(m, vals[i]);
    }
#pragma unroll
    for (int o = 16; o; o >>= 1) m = fmaxf(m, __shfl_xor_sync(0xffffffffu, m, o));
    if ((tid & 31) == 0) red[tid >> 5] = m;
    __syncthreads();
    float bm = red[0];
#pragma unroll
    for (int i = 1; i < 8; i++) bm = fmaxf(bm, red[i]);
    __syncthreads();

    float s = 0.f;
#pragma unroll
    for (int i = 0; i < 8; i++) {
        vals[i] = __expf(vals[i] - bm);
        s += vals[i];
    }
#pragma unroll
    for (int o = 16; o; o >>= 1) s += __shfl_xor_sync(0xffffffffu, s, o);
    if ((tid & 31) == 0) red[tid >> 5] = s;
    __syncthreads();
    float tot = 0.f;
#pragma unroll
    for (int i = 0; i < 8; i++) tot += red[i];
    float inv = 1.0f / tot;
#pragma unroll
    for (int i = 0; i < 8; i++)
        g_P[ro + tid + i * 256] = __float2half(vals[i] * inv);
}

// ================= Stage 4: O = P * V (single fp16) ============================
#define V_OFF_A  0
#define V_OFF_B  10240
#define V_STAGE  20480

__global__ __launch_bounds__(256, 2) void pv_kernel(float* __restrict__ out)
{
    const int z = blockIdx.z;
    const size_t so = (size_t)z * SEQ * SEQ;
    const size_t vo = (size_t)z * SEQ * CH;
    const int rowBlock = blockIdx.y * 128;
    const int colBlock = blockIdx.x * 128;

    const __half* A = g_P + so;
    const __half* B = g_Vh + vo;   // [k][n] MN-major

    const int tid  = threadIdx.x;
    const int lane = tid & 31;
    const int wid  = tid >> 5;
    const int warpRow = wid & 3;
    const int warpCol = wid >> 2;
    const uint32_t sbase = smem_u32(dsmem);

    float acc[2][8][4];
#pragma unroll
    for (int mt = 0; mt < 2; mt++)
#pragma unroll
        for (int nt = 0; nt < 8; nt++)
#pragma unroll
            for (int e = 0; e < 4; e++) acc[mt][nt][e] = 0.f;

    const uint32_t aOff  = ((warpRow * 32 + (lane & 15)) * LDA + ((lane >> 4) << 3)) * 2;
    const uint32_t bOffT = ((lane & 15) * LDBT + warpCol * 64 + ((lane >> 4) << 3)) * 2;

    const int ntiles = SEQ >> 5;    // 64

    ld_km(sbase + V_OFF_A, A, SEQ, rowBlock, 0, tid);
    ld_mn(sbase + V_OFF_B, B, CH, colBlock, 0, tid);
    CP_COMMIT();
    ld_km(sbase + V_STAGE + V_OFF_A, A, SEQ, rowBlock, 32, tid);
    ld_mn(sbase + V_STAGE + V_OFF_B, B, CH, colBlock, 32, tid);
    CP_COMMIT();

    for (int kt = 0; kt < ntiles; kt++) {
        if (kt + 1 < ntiles) { CP_WAIT1(); } else { CP_WAIT0(); }
        __syncthreads();

        const uint32_t sb = sbase + (kt & 1) * V_STAGE;
#pragma unroll
        for (int ks = 0; ks < 2; ks++) {
            const int kb = ks * 16;
            uint32_t ah[2][4];
#pragma unroll
            for (int mt = 0; mt < 2; mt++) {
                uint32_t ad = sb + V_OFF_A + aOff + (mt * 16 * LDA + kb) * 2;
                LDMATRIX_X4(ah[mt][0], ah[mt][1], ah[mt][2], ah[mt][3], ad);
            }
#pragma unroll
            for (int np = 0; np < 4; np++) {
                uint32_t bt[4];
                uint32_t bd = sb + V_OFF_B + bOffT + (kb * LDBT + np * 16) * 2;
                LDMATRIX_X4_T(bt[0], bt[1], bt[2], bt[3], bd);
#pragma unroll
                for (int half = 0; half < 2; half++) {
                    uint32_t b0 = bt[half * 2], b1 = bt[half * 2 + 1];
#pragma unroll
                    for (int mt = 0; mt < 2; mt++) {
                        int nt = np * 2 + half;
                        mma_fp16(acc[mt][nt], ah[mt][0], ah[mt][1], ah[mt][2], ah[mt][3], b0, b1);
                    }
                }
            }
        }
        __syncthreads();

        if (kt + 2 < ntiles) {
            const uint32_t sb2 = sbase + (kt & 1) * V_STAGE;
            const int k0 = (kt + 2) * 32;
            ld_km(sb2 + V_OFF_A, A, SEQ, rowBlock, k0, tid);
            ld_mn(sb2 + V_OFF_B, B, CH, colBlock, k0, tid);
            CP_COMMIT();
        }
    }

    float* O = out + vo;
#pragma unroll
    for (int mt = 0; mt < 2; mt++) {
#pragma unroll
        for (int nt = 0; nt < 8; nt++) {
            int row = rowBlock + warpRow * 32 + mt * 16 + (lane >> 2);
            int col = colBlock + warpCol * 64 + nt * 8 + (lane & 3) * 2;
            *(float2*)(O + (size_t)row * CH + col) =
                make_float2(acc[mt][nt][0], acc[mt][nt][1]);
            *(float2*)(O + (size_t)(row + 8) * CH + col) =
                make_float2(acc[mt][nt][2], acc[mt][nt][3]);
        }
    }
}

// ---------------------------------------------------------------------------
extern "C" void kernel_launch(void* const* d_in, const int* in_sizes, int n_in,
                              void* d_out, int out_size)
{
    const float* q  = (const float*)d_in[0];
    const float* k  = (const float*)d_in[1];
    const float* v  = (const float*)d_in[2];
    const float* Wq = (const float*)d_in[3];
    const float* bq = (const float*)d_in[4];
    const float* Wk = (const float*)d_in[5];
    const float* bk = (const float*)d_in[6];
    const float* Wv = (const float*)d_in[7];
    const float* bv = (const float*)d_in[8];
    float* out = (float*)d_out;

    static int configured = 0;
    if (!configured) {
        cudaFuncSetAttribute(proj_kernel, cudaFuncAttributeMaxDynamicSharedMemorySize, 2 * P_STAGE);
        cudaFuncSetAttribute(qk_kernel,   cudaFuncAttributeMaxDynamicSharedMemorySize, 2 * Q_STAGE);
        cudaFuncSetAttribute(pv_kernel,   cudaFuncAttributeMaxDynamicSharedMemorySize, 2 * V_STAGE);
        configured = 1;
    }

    dim3 gPre(8192, 1, 6);
    pre_kernel<<<gPre, 256>>>(q, k, v, Wq, Wk, Wv);

    dim3 gProj(CH / 128, ROWS / 128, 3);      // (4, 128, 3)
    proj_kernel<<<gProj, 256, 2 * P_STAGE>>>(bq, bk, bv);

    dim3 gQK(SEQ / 128, SEQ / 128, BATCH);    // (16, 16, 8)
    qk_kernel<<<gQK, 256, 2 * Q_STAGE>>>();

    softmax_kernel<<<ROWS, 256>>>();          // 16384 rows

    dim3 gPV(CH / 128, SEQ / 128, BATCH);     // (4, 16, 8)
    pv_kernel<<<gPV, 256, 2 * V_STAGE>>>(out);
}

// round 11
// speedup vs baseline: 2.0095x; 1.0807x over previous
#include <cuda_runtime.h>
#include <cuda_bf16.h>
#include <cuda_fp16.h>
#include <cstdint>

#define BATCH 8
#define SEQ   2048
#define CH    512
#define ROWS  (BATCH * SEQ)          // 16384
#define SCALE 0.25f
#define RC    ((size_t)ROWS * CH)    // 8388608
#define SS    ((size_t)BATCH * SEQ * SEQ)

// ---------------- persistent scratch ----------------
__device__ __half g_Ihf[3 * RC], g_Ilf[3 * RC];   // inputs q,k,v split fp16 hi/lo
__device__ __half g_Wf[3 * CH * CH];              // weights single fp16
__device__ __half g_Qh[RC];             // Q projected, pre-scaled, fp16
__device__ __half g_Kh[RC];             // K projected, fp16
__device__ __half g_Vh[RC];             // V projected, fp16
__device__ float  g_S[SS];              // raw scores fp32
__device__ __half g_P[SS];              // softmax probs, fp16

// ---------------- tiling ----------------
#define BK    64        // K-tile depth
#define LDA   72        // K-major smem pitch, elems (144 B rows; mod-128 spread OK)
#define LDBT  136       // trans-B smem pitch, elems (272 B rows)

extern __shared__ char dsmem[];

// ---------------- PTX helpers ----------------
__device__ __forceinline__ uint32_t smem_u32(const void* p) {
    uint32_t a;
    asm("{ .reg .u64 t; cvta.to.shared.u64 t, %1; cvt.u32.u64 %0, t; }"
        : "=r"(a) : "l"(p));
    return a;
}
__device__ __forceinline__ void cp16(uint32_t dst, const void* src) {
    asm volatile("cp.async.cg.shared.global [%0], [%1], 16;" :: "r"(dst), "l"(src));
}
#define CP_COMMIT() asm volatile("cp.async.commit_group;" ::: "memory")
#define CP_WAIT0()  asm volatile("cp.async.wait_group 0;" ::: "memory")
#define CP_WAIT1()  asm volatile("cp.async.wait_group 1;" ::: "memory")

#define LDMATRIX_X4(r0, r1, r2, r3, addr) \
    asm volatile("ldmatrix.sync.aligned.m8n8.x4.shared.b16 {%0,%1,%2,%3}, [%4];" \
                 : "=r"(r0), "=r"(r1), "=r"(r2), "=r"(r3) : "r"(addr))
#define LDMATRIX_X4_T(r0, r1, r2, r3, addr) \
    asm volatile("ldmatrix.sync.aligned.m8n8.x4.trans.shared.b16 {%0,%1,%2,%3}, [%4];" \
                 : "=r"(r0), "=r"(r1), "=r"(r2), "=r"(r3) : "r"(addr))

__device__ __forceinline__ void mma_fp16(float* c,
                                         uint32_t a0, uint32_t a1, uint32_t a2, uint32_t a3,
                                         uint32_t b0, uint32_t b1) {
    asm volatile(
        "mma.sync.aligned.m16n8k16.row.col.f32.f16.f16.f32 "
        "{%0,%1,%2,%3}, {%4,%5,%6,%7}, {%8,%9}, {%0,%1,%2,%3};"
        : "+f"(c[0]), "+f"(c[1]), "+f"(c[2]), "+f"(c[3])
        : "r"(a0), "r"(a1), "r"(a2), "r"(a3), "r"(b0), "r"(b1));
}

__device__ __forceinline__ void split2h(float x, float y, uint32_t& hi, uint32_t& lo) {
    __half hx = __float2half(x);
    __half hy = __float2half(y);
    __half lx = __float2half(x - __half2float(hx));
    __half ly = __float2half(y - __half2float(hy));
    __half2 H = __halves2half2(hx, hy);
    __half2 L = __halves2half2(lx, ly);
    hi = *reinterpret_cast<uint32_t*>(&H);
    lo = *reinterpret_cast<uint32_t*>(&L);
}

// ---------------- tile loaders (cp.async) ----------------
// K-major [row][k] tile: 128 rows x 64 k, dst pitch 144B. 1024 chunks / 256 thr.
__device__ __forceinline__ void ld_km(uint32_t dst, const __half* src,
                                      int ld, int rowBlock, int k0, int tid)
{
#pragma unroll
    for (int i = 0; i < 4; i++) {
        int c = i * 256 + tid;
        int r = c >> 3, j = c & 7;
        cp16(dst + r * 144 + j * 16, src + (size_t)(rowBlock + r) * ld + k0 + j * 8);
    }
}
// MN-major [k][n] tile: 64 k-rows x 128 n, dst pitch 272B. 1024 chunks / 256 thr.
__device__ __forceinline__ void ld_mn(uint32_t dst, const __half* src,
                                      int ld, int colBlock, int k0, int tid)
{
#pragma unroll
    for (int i = 0; i < 4; i++) {
        int c = i * 256 + tid;
        int k = c >> 4, j = c & 15;
        cp16(dst + k * 272 + j * 16, src + (size_t)(k0 + k) * ld + colBlock + j * 8);
    }
}

// ================= Stage 0: inputs -> fp16 hi/lo, weights -> fp16 ==============
__global__ __launch_bounds__(256) void pre_kernel(
    const float* __restrict__ q, const float* __restrict__ k, const float* __restrict__ v,
    const float* __restrict__ Wq, const float* __restrict__ Wk, const float* __restrict__ Wv)
{
    const int z = blockIdx.z;
    if (z < 3) {
        const float* src = (z == 0) ? q : (z == 1) ? k : v;
        __half* hi = g_Ihf + (size_t)z * RC;
        __half* lo = g_Ilf + (size_t)z * RC;
        size_t i4 = (size_t)blockIdx.x * 256 + threadIdx.x;
        if (i4 >= RC / 4) return;
        float4 val = ((const float4*)src)[i4];
        uint32_t h01, l01, h23, l23;
        split2h(val.x, val.y, h01, l01);
        split2h(val.z, val.w, h23, l23);
        *(uint2*)(hi + i4 * 4) = make_uint2(h01, h23);
        *(uint2*)(lo + i4 * 4) = make_uint2(l01, l23);
    } else {
        const int w = z - 3;
        const float* src = (w == 0) ? Wq : (w == 1) ? Wk : Wv;
        __half* dst = g_Wf + (size_t)w * CH * CH;
        size_t i4 = (size_t)blockIdx.x * 256 + threadIdx.x;
        if (i4 >= (size_t)CH * CH / 4) return;
        float4 val = ((const float4*)src)[i4];
        __half2 p0 = __halves2half2(__float2half(val.x), __float2half(val.y));
        __half2 p1 = __halves2half2(__float2half(val.z), __float2half(val.w));
        uint2 o;
        o.x = *reinterpret_cast<uint32_t*>(&p0);
        o.y = *reinterpret_cast<uint32_t*>(&p1);
        *(uint2*)(dst + i4 * 4) = o;
    }
}

// ================= Stage 1: projections (fp16 2-term: Ihi,Ilo x W) =============
#define P_OFF_AH 0
#define P_OFF_AL 18432
#define P_OFF_B  36864
#define P_STAGE  54272

__global__ __launch_bounds__(256, 2) void proj_kernel(
    const float* __restrict__ bq, const float* __restrict__ bk, const float* __restrict__ bv)
{
    const int z = blockIdx.z;
    const __half* Ah = g_Ihf + (size_t)z * RC;
    const __half* Al = g_Ilf + (size_t)z * RC;
    const __half* B  = g_Wf + (size_t)z * CH * CH;   // [k][n] MN-major
    const float* bias = (z == 0) ? bq : (z == 1) ? bk : bv;
    __half* dst = (z == 0) ? g_Qh : (z == 1) ? g_Kh : g_Vh;
    const float alpha = (z == 0) ? SCALE : 1.0f;

    const int rowBlock = blockIdx.y * 128;
    const int colBlock = blockIdx.x * 128;

    const int tid  = threadIdx.x;
    const int lane = tid & 31;
    const int wid  = tid >> 5;
    const int warpRow = wid & 3;
    const int warpCol = wid >> 2;
    const uint32_t sbase = smem_u32(dsmem);

    float acc[2][8][4];
#pragma unroll
    for (int mt = 0; mt < 2; mt++)
#pragma unroll
        for (int nt = 0; nt < 8; nt++)
#pragma unroll
            for (int e = 0; e < 4; e++) acc[mt][nt][e] = 0.f;

    const uint32_t aOff  = ((warpRow * 32 + (lane & 15)) * LDA + ((lane >> 4) << 3)) * 2;
    const uint32_t bOffT = ((lane & 15) * LDBT + warpCol * 64 + ((lane >> 4) << 3)) * 2;

    const int ntiles = CH / BK;    // 8

    ld_km(sbase + P_OFF_AH, Ah, CH, rowBlock, 0, tid);
    ld_km(sbase + P_OFF_AL, Al, CH, rowBlock, 0, tid);
    ld_mn(sbase + P_OFF_B,  B,  CH, colBlock, 0, tid);
    CP_COMMIT();
    ld_km(sbase + P_STAGE + P_OFF_AH, Ah, CH, rowBlock, BK, tid);
    ld_km(sbase + P_STAGE + P_OFF_AL, Al, CH, rowBlock, BK, tid);
    ld_mn(sbase + P_STAGE + P_OFF_B,  B,  CH, colBlock, BK, tid);
    CP_COMMIT();

    for (int kt = 0; kt < ntiles; kt++) {
        if (kt + 1 < ntiles) { CP_WAIT1(); } else { CP_WAIT0(); }
        __syncthreads();

        const uint32_t sb = sbase + (kt & 1) * P_STAGE;
#pragma unroll
        for (int ks = 0; ks < 4; ks++) {
            const int kb = ks * 16;
            uint32_t ah[2][4], al[2][4];
#pragma unroll
            for (int mt = 0; mt < 2; mt++) {
                uint32_t ad = sb + aOff + (mt * 16 * LDA + kb) * 2;
                LDMATRIX_X4(ah[mt][0], ah[mt][1], ah[mt][2], ah[mt][3], ad + P_OFF_AH);
                LDMATRIX_X4(al[mt][0], al[mt][1], al[mt][2], al[mt][3], ad + P_OFF_AL);
            }
#pragma unroll
            for (int np = 0; np < 4; np++) {
                uint32_t bt[4];
                uint32_t bd = sb + P_OFF_B + bOffT + (kb * LDBT + np * 16) * 2;
                LDMATRIX_X4_T(bt[0], bt[1], bt[2], bt[3], bd);
#pragma unroll
                for (int half = 0; half < 2; half++) {
                    uint32_t b0 = bt[half * 2], b1 = bt[half * 2 + 1];
#pragma unroll
                    for (int mt = 0; mt < 2; mt++) {
                        int nt = np * 2 + half;
                        mma_fp16(acc[mt][nt], ah[mt][0], ah[mt][1], ah[mt][2], ah[mt][3], b0, b1);
                        mma_fp16(acc[mt][nt], al[mt][0], al[mt][1], al[mt][2], al[mt][3], b0, b1);
                    }
                }
            }
        }
        __syncthreads();

        if (kt + 2 < ntiles) {
            const uint32_t sb2 = sbase + (kt & 1) * P_STAGE;
            const int k0 = (kt + 2) * BK;
            ld_km(sb2 + P_OFF_AH, Ah, CH, rowBlock, k0, tid);
            ld_km(sb2 + P_OFF_AL, Al, CH, rowBlock, k0, tid);
            ld_mn(sb2 + P_OFF_B,  B,  CH, colBlock, k0, tid);
            CP_COMMIT();
        }
    }

#pragma unroll
    for (int mt = 0; mt < 2; mt++) {
#pragma unroll
        for (int nt = 0; nt < 8; nt++) {
            int row = rowBlock + warpRow * 32 + mt * 16 + (lane >> 2);
            int col = colBlock + warpCol * 64 + nt * 8 + (lane & 3) * 2;
            float2 b = *(const float2*)(bias + col);
            float x0 = (acc[mt][nt][0] + b.x) * alpha;
            float y0 = (acc[mt][nt][1] + b.y) * alpha;
            float x1 = (acc[mt][nt][2] + b.x) * alpha;
            float y1 = (acc[mt][nt][3] + b.y) * alpha;
            size_t o0 = (size_t)row * CH + col;
            size_t o1 = (size_t)(row + 8) * CH + col;
            *(__half2*)(dst + o0) = __halves2half2(__float2half(x0), __float2half(y0));
            *(__half2*)(dst + o1) = __halves2half2(__float2half(x1), __float2half(y1));
        }
    }
}

// ================= Stage 2: S = Q*K^T (single-term fp16) =======================
#define Q_OFF_A  0
#define Q_OFF_B  18432
#define Q_STAGE  36864

__global__ __launch_bounds__(256, 2) void qk_kernel()
{
    const int z = blockIdx.z;
    const size_t po = (size_t)z * SEQ * CH;
    float* S = g_S + (size_t)z * SEQ * SEQ;
    const int rowBlock = blockIdx.y * 128;
    const int colBlock = blockIdx.x * 128;

    const __half* A = g_Qh + po;
    const __half* B = g_Kh + po;

    const int tid  = threadIdx.x;
    const int lane = tid & 31;
    const int wid  = tid >> 5;
    const int warpRow = wid & 3;
    const int warpCol = wid >> 2;
    const uint32_t sbase = smem_u32(dsmem);

    float acc[2][8][4];
#pragma unroll
    for (int mt = 0; mt < 2; mt++)
#pragma unroll
        for (int nt = 0; nt < 8; nt++)
#pragma unroll
            for (int e = 0; e < 4; e++) acc[mt][nt][e] = 0.f;

    const uint32_t aOff = ((warpRow * 32 + (lane & 15)) * LDA + ((lane >> 4) << 3)) * 2;
    const uint32_t bOff = ((warpCol * 64 + ((lane >> 4) << 3) + (lane & 7)) * LDA
                          + (((lane >> 3) & 1) << 3)) * 2;

    const int ntiles = CH / BK;    // 8

    ld_km(sbase + Q_OFF_A, A, CH, rowBlock, 0, tid);
    ld_km(sbase + Q_OFF_B, B, CH, colBlock, 0, tid);
    CP_COMMIT();
    ld_km(sbase + Q_STAGE + Q_OFF_A, A, CH, rowBlock, BK, tid);
    ld_km(sbase + Q_STAGE + Q_OFF_B, B, CH, colBlock, BK, tid);
    CP_COMMIT();

    for (int kt = 0; kt < ntiles; kt++) {
        if (kt + 1 < ntiles) { CP_WAIT1(); } else { CP_WAIT0(); }
        __syncthreads();

        const uint32_t sb = sbase + (kt & 1) * Q_STAGE;
#pragma unroll
        for (int ks = 0; ks < 4; ks++) {
            const int kb = ks * 16;
            uint32_t ah[2][4];
#pragma unroll
            for (int mt = 0; mt < 2; mt++) {
                uint32_t ad = sb + Q_OFF_A + aOff + (mt * 16 * LDA + kb) * 2;
                LDMATRIX_X4(ah[mt][0], ah[mt][1], ah[mt][2], ah[mt][3], ad);
            }
#pragma unroll
            for (int np = 0; np < 4; np++) {
                uint32_t bh[4];
                uint32_t bd = sb + Q_OFF_B + bOff + (np * 16 * LDA + kb) * 2;
                LDMATRIX_X4(bh[0], bh[1], bh[2], bh[3], bd);
#pragma unroll
                for (int half = 0; half < 2; half++) {
                    uint32_t b0 = bh[half * 2], b1 = bh[half * 2 + 1];
#pragma unroll
                    for (int mt = 0; mt < 2; mt++) {
                        int nt = np * 2 + half;
                        mma_fp16(acc[mt][nt], ah[mt][0], ah[mt][1], ah[mt][2], ah[mt][3], b0, b1);
                    }
                }
            }
        }
        __syncthreads();

        if (kt + 2 < ntiles) {
            const uint32_t sb2 = sbase + (kt & 1) * Q_STAGE;
            const int k0 = (kt + 2) * BK;
            ld_km(sb2 + Q_OFF_A, A, CH, rowBlock, k0, tid);
            ld_km(sb2 + Q_OFF_B, B, CH, colBlock, k0, tid);
            CP_COMMIT();
        }
    }

#pragma unroll
    for (int mt = 0; mt < 2; mt++) {
#pragma unroll
        for (int nt = 0; nt < 8; nt++) {
            int row = rowBlock + warpRow * 32 + mt * 16 + (lane >> 2);
            int col = colBlock + warpCol * 64 + nt * 8 + (lane & 3) * 2;
            *(float2*)(S + (size_t)row * SEQ + col) =
                make_float2(acc[mt][nt][0], acc[mt][nt][1]);
            *(float2*)(S + (size_t)(row + 8) * SEQ + col) =
                make_float2(acc[mt][nt][2], acc[mt][nt][3]);
        }
    }
}

// ================= Stage 3: softmax -> single fp16 probs =======================
__global__ __launch_bounds__(256) void softmax_kernel()
{
    __shared__ float red[8];
    const size_t ro = (size_t)blockIdx.x * SEQ;
    const float* row = g_S + ro;
    const int tid = threadIdx.x;

    float vals[8];
    float m = -3.0e38f;
#pragma unroll
    for (int i = 0; i < 8; i++) {
        vals[i] = row[tid + i * 256];
        m = fmaxf(m, vals[i]);
    }
#pragma unroll
    for (int o = 16; o; o >>= 1) m = fmaxf(m, __shfl_xor_sync(0xffffffffu, m, o));
    if ((tid & 31) == 0) red[tid >> 5] = m;
    __syncthreads();
    float bm = red[0];
#pragma unroll
    for (int i = 1; i < 8; i++) bm = fmaxf(bm, red[i]);
    __syncthreads();

    float s = 0.f;
#pragma unroll
    for (int i = 0; i < 8; i++) {
        vals[i] = __expf(vals[i] - bm);
        s += vals[i];
    }
#pragma unroll
    for (int o = 16; o; o >>= 1) s += __shfl_xor_sync(0xffffffffu, s, o);
    if ((tid & 31) == 0) red[tid >> 5] = s;
    __syncthreads();
    float tot = 0.f;
#pragma unroll
    for (int i = 0; i < 8; i++) tot += red[i];
    float inv = 1.0f / tot;
#pragma unroll
    for (int i = 0; i < 8; i++)
        g_P[ro + tid + i * 256] = __float2half(vals[i] * inv);
}

// ================= Stage 4: O = P * V (single fp16) ============================
#define V_OFF_A  0
#define V_OFF_B  18432
#define V_STAGE  35840

__global__ __launch_bounds__(256, 2) void pv_kernel(float* __restrict__ out)
{
    const int z = blockIdx.z;
    const size_t so = (size_t)z * SEQ * SEQ;
    const size_t vo = (size_t)z * SEQ * CH;
    const int rowBlock = blockIdx.y * 128;
    const int colBlock = blockIdx.x * 128;

    const __half* A = g_P + so;
    const __half* B = g_Vh + vo;   // [k][n] MN-major

    const int tid  = threadIdx.x;
    const int lane = tid & 31;
    const int wid  = tid >> 5;
    const int warpRow = wid & 3;
    const int warpCol = wid >> 2;
    const uint32_t sbase = smem_u32(dsmem);

    float acc[2][8][4];
#pragma unroll
    for (int mt = 0; mt < 2; mt++)
#pragma unroll
        for (int nt = 0; nt < 8; nt++)
#pragma unroll
            for (int e = 0; e < 4; e++) acc[mt][nt][e] = 0.f;

    const uint32_t aOff  = ((warpRow * 32 + (lane & 15)) * LDA + ((lane >> 4) << 3)) * 2;
    const uint32_t bOffT = ((lane & 15) * LDBT + warpCol * 64 + ((lane >> 4) << 3)) * 2;

    const int ntiles = SEQ / BK;    // 32

    ld_km(sbase + V_OFF_A, A, SEQ, rowBlock, 0, tid);
    ld_mn(sbase + V_OFF_B, B, CH, colBlock, 0, tid);
    CP_COMMIT();
    ld_km(sbase + V_STAGE + V_OFF_A, A, SEQ, rowBlock, BK, tid);
    ld_mn(sbase + V_STAGE + V_OFF_B, B, CH, colBlock, BK, tid);
    CP_COMMIT();

    for (int kt = 0; kt < ntiles; kt++) {
        if (kt + 1 < ntiles) { CP_WAIT1(); } else { CP_WAIT0(); }
        __syncthreads();

        const uint32_t sb = sbase + (kt & 1) * V_STAGE;
#pragma unroll
        for (int ks = 0; ks < 4; ks++) {
            const int kb = ks * 16;
            uint32_t ah[2][4];
#pragma unroll
            for (int mt = 0; mt < 2; mt++) {
                uint32_t ad = sb + V_OFF_A + aOff + (mt * 16 * LDA + kb) * 2;
                LDMATRIX_X4(ah[mt][0], ah[mt][1], ah[mt][2], ah[mt][3], ad);
            }
#pragma unroll
            for (int np = 0; np < 4; np++) {
                uint32_t bt[4];
                uint32_t bd = sb + V_OFF_B + bOffT + (kb * LDBT + np * 16) * 2;
                LDMATRIX_X4_T(bt[0], bt[1], bt[2], bt[3], bd);
#pragma unroll
                for (int half = 0; half < 2; half++) {
                    uint32_t b0 = bt[half * 2], b1 = bt[half * 2 + 1];
#pragma unroll
                    for (int mt = 0; mt < 2; mt++) {
                        int nt = np * 2 + half;
                        mma_fp16(acc[mt][nt], ah[mt][0], ah[mt][1], ah[mt][2], ah[mt][3], b0, b1);
                    }
                }
            }
        }
        __syncthreads();

        if (kt + 2 < ntiles) {
            const uint32_t sb2 = sbase + (kt & 1) * V_STAGE;
            const int k0 = (kt + 2) * BK;
            ld_km(sb2 + V_OFF_A, A, SEQ, rowBlock, k0, tid);
            ld_mn(sb2 + V_OFF_B, B, CH, colBlock, k0, tid);
            CP_COMMIT();
        }
    }

    float* O = out + vo;
#pragma unroll
    for (int mt = 0; mt < 2; mt++) {
#pragma unroll
        for (int nt = 0; nt < 8; nt++) {
            int row = rowBlock + warpRow * 32 + mt * 16 + (lane >> 2);
            int col = colBlock + warpCol * 64 + nt * 8 + (lane & 3) * 2;
            *(float2*)(O + (size_t)row * CH + col) =
                make_float2(acc[mt][nt][0], acc[mt][nt][1]);
            *(float2*)(O + (size_t)(row + 8) * CH + col) =
                make_float2(acc[mt][nt][2], acc[mt][nt][3]);
        }
    }
}

// ---------------------------------------------------------------------------
extern "C" void kernel_launch(void* const* d_in, const int* in_sizes, int n_in,
                              void* d_out, int out_size)
{
    const float* q  = (const float*)d_in[0];
    const float* k  = (const float*)d_in[1];
    const float* v  = (const float*)d_in[2];
    const float* Wq = (const float*)d_in[3];
    const float* bq = (const float*)d_in[4];
    const float* Wk = (const float*)d_in[5];
    const float* bk = (const float*)d_in[6];
    const float* Wv = (const float*)d_in[7];
    const float* bv = (const float*)d_in[8];
    float* out = (float*)d_out;

    static int configured = 0;
    if (!configured) {
        cudaFuncSetAttribute(proj_kernel, cudaFuncAttributeMaxDynamicSharedMemorySize, 2 * P_STAGE);
        cudaFuncSetAttribute(qk_kernel,   cudaFuncAttributeMaxDynamicSharedMemorySize, 2 * Q_STAGE);
        cudaFuncSetAttribute(pv_kernel,   cudaFuncAttributeMaxDynamicSharedMemorySize, 2 * V_STAGE);
        configured = 1;
    }

    dim3 gPre(8192, 1, 6);
    pre_kernel<<<gPre, 256>>>(q, k, v, Wq, Wk, Wv);

    dim3 gProj(CH / 128, ROWS / 128, 3);      // (4, 128, 3)
    proj_kernel<<<gProj, 256, 2 * P_STAGE>>>(bq, bk, bv);

    dim3 gQK(SEQ / 128, SEQ / 128, BATCH);    // (16, 16, 8)
    qk_kernel<<<gQK, 256, 2 * Q_STAGE>>>();

    softmax_kernel<<<ROWS, 256>>>();          // 16384 rows

    dim3 gPV(CH / 128, SEQ / 128, BATCH);     // (4, 16, 8)
    pv_kernel<<<gPV, 256, 2 * V_STAGE>>>(out);
}